// round 8
// baseline (speedup 1.0000x reference)
#include <cuda_runtime.h>
#include <cstdint>

// Problem dims (fixed): B=4, N=2048, F_in=128, H=4, D=32
#define Bn 4
#define Nn 2048
#define Fn 128
#define Hn 4
#define Dn 32
#define BH (Bn*Hn)
#define LOG2E 1.4426950408889634f
#define FULLM 0xffffffffu

// Scratch (device globals; no allocation allowed). 16B+ alignment for vector access.
__device__ __align__(256) float g_Wh[BH * Nn * Dn];   // [bh][n][d], tf32-rounded values
__device__ __align__(16)  float g_es[BH * Nn];        // e_src (exact fp32)
__device__ __align__(16)  float g_ed[BH * Nn];        // e_dst (exact fp32)

// -------------------- Kernel A: projection + e_src/e_dst --------------------
__global__ __launch_bounds__(128) void proj_kernel(
    const float* __restrict__ h, const float* __restrict__ W,
    const float* __restrict__ a)
{
    __shared__ __align__(16) float h_sm[16 * Fn];
    const int b  = blockIdx.x;
    const int n0 = blockIdx.y * 16;

    const float4* hsrc = (const float4*)(h + (size_t)(b * Nn + n0) * Fn);
    float4* hdst = (float4*)h_sm;
    #pragma unroll
    for (int r = 0; r < 4; r++) hdst[threadIdx.x + r * 128] = hsrc[threadIdx.x + r * 128];
    __syncthreads();

    const int warp = threadIdx.x >> 5;   // head
    const int lane = threadIdx.x & 31;   // d

    const float* Wp = W + (warp * Fn) * Dn + lane;
    float acc[16];
    #pragma unroll
    for (int n = 0; n < 16; n++) acc[n] = 0.f;

    #pragma unroll 4
    for (int f = 0; f < Fn; f++) {
        float w = __ldg(Wp + f * Dn);
        #pragma unroll
        for (int n = 0; n < 16; n++)
            acc[n] = fmaf(h_sm[n * Fn + f], w, acc[n]);
    }

    const float a_s = __ldg(a + warp * (2 * Dn) + lane);
    const float a_d = __ldg(a + warp * (2 * Dn) + Dn + lane);

    const int bh = b * Hn + warp;
    float* whp = g_Wh + ((size_t)bh * Nn + n0) * Dn + lane;

    #pragma unroll
    for (int n = 0; n < 16; n++) {
        // es/ed from EXACT acc (softmax row-max exactness); store Wh rounded to tf32
        float es = acc[n] * a_s;
        float ed = acc[n] * a_d;
        uint32_t t;
        asm("cvt.rna.tf32.f32 %0, %1;" : "=r"(t) : "f"(acc[n]));
        whp[n * Dn] = __uint_as_float(t);
        #pragma unroll
        for (int off = 16; off; off >>= 1) {
            es += __shfl_xor_sync(FULLM, es, off);
            ed += __shfl_xor_sync(FULLM, ed, off);
        }
        if (lane == 0) {
            g_es[bh * Nn + n0 + n] = es;
            g_ed[bh * Nn + n0 + n] = ed;
        }
    }
}

// -------------------- Kernel B: masked softmax + P@Wh via tf32 MMA --------------------
// Block: 128 threads / 4 warps / 32 rows. Warp w: rows (w&1)*16..+16, j-slices of
// parity (w>>1) (32 j per meta-step). All warps compute every step; C/l combined via
// smem at the end. Exact row max from pass 1 (full row) shared by both parities.
#define TJm 64            // j per meta (two 32-j parity slices)
#define NMT (Nn / TJm)    // 32 metas
#define WST 40            // wh_sm row stride (floats)
#define CST 34            // C-scratch row stride (floats, even -> 8B aligned float2)

__global__ __launch_bounds__(128, 6) void attn_kernel(
    const int* __restrict__ adj, float* __restrict__ out)
{
    __shared__ __align__(16) float    ed_sm[Nn];            // 8 KB (e_dst * LOG2E)
    __shared__ __align__(16) unsigned mask_sm[32 * 64];     // 8 KB adjacency bits (reused as C scratch)
    __shared__ __align__(16) float    wh_sm[2][TJm * WST];  // 20 KB double buffer
    __shared__ float es_sm[32], M_sm[32], nz_sm[32];

    const int bh = blockIdx.x;
    const int b  = bh >> 2;
    const int hd = bh & 3;
    const int rbase = blockIdx.y * 32;
    const int tid  = threadIdx.x;
    const int warp = tid >> 5;
    const int lane = tid & 31;
    const int g  = lane >> 2;      // groupID (row mod 8 within 16)
    const int qt = lane & 3;       // thread-in-group (k/col selector)
    const int par = warp >> 1;     // j parity
    const int lrA = (warp & 1) * 16 + g;   // local row A
    const int lrB = lrA + 8;               // local row B

    const float* whg = g_Wh + (size_t)bh * Nn * Dn;

    // ---- stage e_dst (scaled to log2 units) ----
    {
        const float4* src = (const float4*)(g_ed + bh * Nn);
        float4* dst = (float4*)ed_sm;
        #pragma unroll
        for (int r = 0; r < 4; r++) {
            float4 v = src[tid + r * 128];
            v.x *= LOG2E; v.y *= LOG2E; v.z *= LOG2E; v.w *= LOG2E;
            dst[tid + r * 128] = v;
        }
    }

    // ---- prologue: prefetch Wh metas 0,1 (overlaps pass 1) ----
    #pragma unroll
    for (int c = 0; c < 2; c++) {
        const float* src = whg + (size_t)(c * TJm) * Dn;
        #pragma unroll
        for (int t = 0; t < 4; t++) {
            int idx = tid + t * 128;
            int row = idx >> 3, c4 = idx & 7;
            uint32_t dp = (uint32_t)__cvta_generic_to_shared(&wh_sm[c][row * WST + c4 * 4]);
            asm volatile("cp.async.ca.shared.global [%0], [%1], 16;"
                         :: "r"(dp), "l"(src + row * Dn + c4 * 4));
        }
        asm volatile("cp.async.commit_group;" ::: "memory");
    }

    __syncthreads();   // ed_sm ready

    // ---- Pass 1: pack adjacency bits + exact masked row max (warp scans 8 rows) ----
    // mask word (r, it*4+c) holds bit L for j = it*128 + L*4 + c
    for (int k = 0; k < 8; k++) {
        const int lr = warp * 8 + k;
        const int r  = rbase + lr;
        const int* adjr = adj + (size_t)r * Nn;
        float m = -1e30f;
        #pragma unroll
        for (int it = 0; it < 16; it++) {
            uint4 av = __ldg((const uint4*)(adjr + it * 128 + lane * 4));
            float4 ev = *(const float4*)(ed_sm + it * 128 + lane * 4);
            unsigned m0 = __ballot_sync(FULLM, (int)av.x > 0);
            unsigned m1 = __ballot_sync(FULLM, (int)av.y > 0);
            unsigned m2 = __ballot_sync(FULLM, (int)av.z > 0);
            unsigned m3 = __ballot_sync(FULLM, (int)av.w > 0);
            if ((int)av.x > 0) m = fmaxf(m, ev.x);
            if ((int)av.y > 0) m = fmaxf(m, ev.y);
            if ((int)av.z > 0) m = fmaxf(m, ev.z);
            if ((int)av.w > 0) m = fmaxf(m, ev.w);
            if (lane == 0)
                *(uint4*)(mask_sm + lr * 64 + it * 4) = make_uint4(m0, m1, m2, m3);
        }
        #pragma unroll
        for (int off = 16; off; off >>= 1) m = fmaxf(m, __shfl_xor_sync(FULLM, m, off));
        if (lane == 0) {
            const float es = __ldg(g_es + bh * Nn + r) * LOG2E;
            float M, nz;
            if (m < -9e29f) { M = 0.f; nz = 1.f; }   // empty row -> uniform (matches ref)
            else { float s = es + m; M = fmaxf(s, 0.2f * s); nz = 0.f; }
            es_sm[lr] = es; M_sm[lr] = M; nz_sm[lr] = nz;
        }
    }
    __syncthreads();   // masks + row stats ready

    const float esA = es_sm[lrA], MA = M_sm[lrA], nzA = nz_sm[lrA];
    const float esB = es_sm[lrB], MB = M_sm[lrB], nzB = nz_sm[lrB];

    // ---- Pass 2: P (A-fragment layout) @ Wh via mma.m16n8k8 tf32 ----
    float C[4][4];
    #pragma unroll
    for (int nt = 0; nt < 4; nt++)
        #pragma unroll
        for (int k = 0; k < 4; k++) C[nt][k] = 0.f;
    float lA = 0.f, lB = 0.f;

    for (int t = 0; t < NMT; t++) {
        asm volatile("cp.async.wait_group 1;" ::: "memory");
        __syncthreads();   // buf[t&1] ready

        const int jb = t * TJm + par * 32;         // this warp's 32-j slice base
        const int wofs = ((t >> 1) << 2) + qt;     // mask word (128-j granule)
        const unsigned wA = mask_sm[lrA * 64 + wofs];
        const unsigned wB = mask_sm[lrB * 64 + wofs];
        const int bs = (t & 1) * 16 + par * 8;     // bit base within word
        const float* wbuf = wh_sm[t & 1] + par * 32 * WST;

        #pragma unroll
        for (int ks = 0; ks < 4; ks++) {
            const int j0 = ks * 8;
            const float ed0 = ed_sm[jb + j0 + qt];
            const float ed4 = ed_sm[jb + j0 + qt + 4];
            float s;
            s = esA + ed0; s = fmaxf(s, 0.2f * s);
            const float pA0 = ((wA >> (bs + 2 * ks)) & 1u) ? exp2f(s - MA) : nzA;
            s = esB + ed0; s = fmaxf(s, 0.2f * s);
            const float pB0 = ((wB >> (bs + 2 * ks)) & 1u) ? exp2f(s - MB) : nzB;
            s = esA + ed4; s = fmaxf(s, 0.2f * s);
            const float pA4 = ((wA >> (bs + 2 * ks + 1)) & 1u) ? exp2f(s - MA) : nzA;
            s = esB + ed4; s = fmaxf(s, 0.2f * s);
            const float pB4 = ((wB >> (bs + 2 * ks + 1)) & 1u) ? exp2f(s - MB) : nzB;
            lA += pA0 + pA4;
            lB += pB0 + pB4;
            uint32_t a0, a1, a2, a3;
            asm("cvt.rna.tf32.f32 %0, %1;" : "=r"(a0) : "f"(pA0));
            asm("cvt.rna.tf32.f32 %0, %1;" : "=r"(a1) : "f"(pB0));
            asm("cvt.rna.tf32.f32 %0, %1;" : "=r"(a2) : "f"(pA4));
            asm("cvt.rna.tf32.f32 %0, %1;" : "=r"(a3) : "f"(pB4));
            const float* w0p = wbuf + (j0 + qt) * WST + g;
            const float* w1p = wbuf + (j0 + qt + 4) * WST + g;
            #pragma unroll
            for (int nt = 0; nt < 4; nt++) {
                const uint32_t b0 = __float_as_uint(w0p[nt * 8]);
                const uint32_t b1 = __float_as_uint(w1p[nt * 8]);
                asm volatile(
                    "mma.sync.aligned.m16n8k8.row.col.f32.tf32.tf32.f32 "
                    "{%0,%1,%2,%3}, {%4,%5,%6,%7}, {%8,%9}, {%0,%1,%2,%3};"
                    : "+f"(C[nt][0]), "+f"(C[nt][1]), "+f"(C[nt][2]), "+f"(C[nt][3])
                    : "r"(a0), "r"(a1), "r"(a2), "r"(a3), "r"(b0), "r"(b1));
            }
        }

        __syncthreads();   // all warps done with buf[t&1]
        const int nc = t + 2;
        if (nc < NMT) {
            const float* src = whg + (size_t)(nc * TJm) * Dn;
            #pragma unroll
            for (int tt = 0; tt < 4; tt++) {
                int idx = tid + tt * 128;
                int row = idx >> 3, c4 = idx & 7;
                uint32_t dp = (uint32_t)__cvta_generic_to_shared(&wh_sm[nc & 1][row * WST + c4 * 4]);
                asm volatile("cp.async.ca.shared.global [%0], [%1], 16;"
                             :: "r"(dp), "l"(src + row * Dn + c4 * 4));
            }
        }
        asm volatile("cp.async.commit_group;" ::: "memory");   // unconditional
    }

    // ---- Combine the two j-parities (warp w and w+2 hold same rows) ----
    #pragma unroll
    for (int off = 1; off < 4; off <<= 1) {
        lA += __shfl_xor_sync(FULLM, lA, off);
        lB += __shfl_xor_sync(FULLM, lB, off);
    }

    float* Csc = (float*)mask_sm;          // masks dead after pass 2
    float* lsc = Csc + 32 * CST;
    if (par == 1) {
        #pragma unroll
        for (int nt = 0; nt < 4; nt++) {
            *(float2*)&Csc[lrA * CST + nt * 8 + 2 * qt] = make_float2(C[nt][0], C[nt][1]);
            *(float2*)&Csc[lrB * CST + nt * 8 + 2 * qt] = make_float2(C[nt][2], C[nt][3]);
        }
        if (qt == 0) { lsc[lrA] = lA; lsc[lrB] = lB; }
    }
    __syncthreads();
    if (par == 0) {
        #pragma unroll
        for (int nt = 0; nt < 4; nt++) {
            float2 cA = *(const float2*)&Csc[lrA * CST + nt * 8 + 2 * qt];
            float2 cB = *(const float2*)&Csc[lrB * CST + nt * 8 + 2 * qt];
            C[nt][0] += cA.x; C[nt][1] += cA.y;
            C[nt][2] += cB.x; C[nt][3] += cB.y;
        }
        const float rlA = 1.f / (lA + lsc[lrA]);
        const float rlB = 1.f / (lB + lsc[lrB]);
        const int iA = rbase + lrA;
        const int iB = rbase + lrB;
        float* outA = out + (size_t)(b * Nn + iA) * (Hn * Dn) + hd * Dn + 2 * qt;
        float* outB = out + (size_t)(b * Nn + iB) * (Hn * Dn) + hd * Dn + 2 * qt;
        #pragma unroll
        for (int nt = 0; nt < 4; nt++) {
            *(float2*)(outA + nt * 8) = make_float2(C[nt][0] * rlA, C[nt][1] * rlA);
            *(float2*)(outB + nt * 8) = make_float2(C[nt][2] * rlB, C[nt][3] * rlB);
        }
    }
}

extern "C" void kernel_launch(void* const* d_in, const int* in_sizes, int n_in,
                              void* d_out, int out_size)
{
    // Bind inputs by element count (robust to metadata ordering)
    const float* h = nullptr; const int* adj = nullptr;
    const float* W = nullptr; const float* a = nullptr;
    for (int i = 0; i < n_in; i++) {
        switch (in_sizes[i]) {
            case 1048576: h   = (const float*)d_in[i]; break;
            case 4194304: adj = (const int*)  d_in[i]; break;
            case 16384:   W   = (const float*)d_in[i]; break;
            case 256:     a   = (const float*)d_in[i]; break;
        }
    }
    float* out = (float*)d_out;

    proj_kernel<<<dim3(Bn, Nn / 16), 128>>>(h, W, a);
    attn_kernel<<<dim3(BH, Nn / 32), 128>>>(adj, out);
}

// round 9
// speedup vs baseline: 1.2430x; 1.2430x over previous
#include <cuda_runtime.h>
#include <cstdint>

// Problem dims (fixed): B=4, N=2048, F_in=128, H=4, D=32
#define Bn 4
#define Nn 2048
#define Fn 128
#define Hn 4
#define Dn 32
#define BH (Bn*Hn)
#define LOG2E 1.4426950408889634f
#define FULLM 0xffffffffu

// Scratch (device globals; no allocation allowed). 16B+ alignment for vector access.
__device__ __align__(256) float g_Wh[BH * Nn * Dn];   // [bh][n][d], tf32-rounded values
__device__ __align__(16)  float g_es[BH * Nn];        // e_src (exact fp32)
__device__ __align__(16)  float g_ed[BH * Nn];        // e_dst (exact fp32)

// -------------------- Kernel A: projection + e_src/e_dst --------------------
__global__ __launch_bounds__(128) void proj_kernel(
    const float* __restrict__ h, const float* __restrict__ W,
    const float* __restrict__ a)
{
    __shared__ __align__(16) float h_sm[16 * Fn];
    const int b  = blockIdx.x;
    const int n0 = blockIdx.y * 16;

    const float4* hsrc = (const float4*)(h + (size_t)(b * Nn + n0) * Fn);
    float4* hdst = (float4*)h_sm;
    #pragma unroll
    for (int r = 0; r < 4; r++) hdst[threadIdx.x + r * 128] = hsrc[threadIdx.x + r * 128];
    __syncthreads();

    const int warp = threadIdx.x >> 5;   // head
    const int lane = threadIdx.x & 31;   // d

    const float* Wp = W + (warp * Fn) * Dn + lane;
    float acc[16];
    #pragma unroll
    for (int n = 0; n < 16; n++) acc[n] = 0.f;

    #pragma unroll 4
    for (int f = 0; f < Fn; f++) {
        float w = __ldg(Wp + f * Dn);
        #pragma unroll
        for (int n = 0; n < 16; n++)
            acc[n] = fmaf(h_sm[n * Fn + f], w, acc[n]);
    }

    const float a_s = __ldg(a + warp * (2 * Dn) + lane);
    const float a_d = __ldg(a + warp * (2 * Dn) + Dn + lane);

    const int bh = b * Hn + warp;
    float* whp = g_Wh + ((size_t)bh * Nn + n0) * Dn + lane;

    #pragma unroll
    for (int n = 0; n < 16; n++) {
        // es/ed from EXACT acc (softmax row-max exactness); store Wh rounded to tf32
        float es = acc[n] * a_s;
        float ed = acc[n] * a_d;
        uint32_t t;
        asm("cvt.rna.tf32.f32 %0, %1;" : "=r"(t) : "f"(acc[n]));
        whp[n * Dn] = __uint_as_float(t);
        #pragma unroll
        for (int off = 16; off; off >>= 1) {
            es += __shfl_xor_sync(FULLM, es, off);
            ed += __shfl_xor_sync(FULLM, ed, off);
        }
        if (lane == 0) {
            g_es[bh * Nn + n0 + n] = es;
            g_ed[bh * Nn + n0 + n] = ed;
        }
    }
}

// -------------------- Kernel B: masked softmax + P@Wh via tf32 MMA --------------------
// Block: 256 threads / 8 warps / 64 rows. Warp w: rows (w&3)*16..+16, j-parity (w>>2)
// (32-j slices alternating within each 64-j meta). Block-level shared work (ed staging,
// Wh stream, adjacency scan) identical to the 106us R7 kernel; warp count doubled.
#define TJm 64            // j per meta (two 32-j parity slices)
#define NMT (Nn / TJm)    // 32 metas
#define WST 40            // wh_sm row stride (floats)
#define CST 34            // C-scratch row stride (floats)

__global__ __launch_bounds__(256, 3) void attn_kernel(
    const int* __restrict__ adj, float* __restrict__ out)
{
    __shared__ __align__(16) float    ed_sm[Nn];            // 8 KB (e_dst * LOG2E)
    __shared__ __align__(16) unsigned mask_sm[64 * 64];     // 16 KB adjacency bits (reused as C scratch)
    __shared__ __align__(16) float    wh_sm[2][TJm * WST];  // 20 KB double buffer
    __shared__ float es_sm[64], M_sm[64], nz_sm[64];

    const int bh = blockIdx.x;
    const int b  = bh >> 2;
    const int hd = bh & 3;
    const int rbase = blockIdx.y * 64;
    const int tid  = threadIdx.x;
    const int warp = tid >> 5;
    const int lane = tid & 31;
    const int g  = lane >> 2;      // groupID (row mod 8 within 16)
    const int qt = lane & 3;       // thread-in-group (k/col selector)
    const int par = warp >> 2;     // j parity
    const int lrA = (warp & 3) * 16 + g;   // local row A
    const int lrB = lrA + 8;               // local row B

    const float* whg = g_Wh + (size_t)bh * Nn * Dn;

    // ---- stage e_dst (scaled to log2 units) ----
    {
        const float4* src = (const float4*)(g_ed + bh * Nn);
        float4* dst = (float4*)ed_sm;
        #pragma unroll
        for (int r = 0; r < 2; r++) {
            float4 v = src[tid + r * 256];
            v.x *= LOG2E; v.y *= LOG2E; v.z *= LOG2E; v.w *= LOG2E;
            dst[tid + r * 256] = v;
        }
    }

    // ---- prologue: prefetch Wh metas 0,1 (overlaps pass 1) ----
    #pragma unroll
    for (int c = 0; c < 2; c++) {
        const float* src = whg + (size_t)(c * TJm) * Dn;
        #pragma unroll
        for (int t = 0; t < 2; t++) {
            int idx = tid + t * 256;
            int row = idx >> 3, c4 = idx & 7;
            uint32_t dp = (uint32_t)__cvta_generic_to_shared(&wh_sm[c][row * WST + c4 * 4]);
            asm volatile("cp.async.ca.shared.global [%0], [%1], 16;"
                         :: "r"(dp), "l"(src + row * Dn + c4 * 4));
        }
        asm volatile("cp.async.commit_group;" ::: "memory");
    }

    __syncthreads();   // ed_sm ready

    // ---- Pass 1: pack adjacency bits + exact masked row max (warp scans 8 rows) ----
    // mask word (r, it*4+c) holds bit L for j = it*128 + L*4 + c
    for (int k = 0; k < 8; k++) {
        const int lr = warp * 8 + k;
        const int r  = rbase + lr;
        const int* adjr = adj + (size_t)r * Nn;
        float m = -1e30f;
        #pragma unroll
        for (int it = 0; it < 16; it++) {
            uint4 av = __ldg((const uint4*)(adjr + it * 128 + lane * 4));
            float4 ev = *(const float4*)(ed_sm + it * 128 + lane * 4);
            unsigned m0 = __ballot_sync(FULLM, (int)av.x > 0);
            unsigned m1 = __ballot_sync(FULLM, (int)av.y > 0);
            unsigned m2 = __ballot_sync(FULLM, (int)av.z > 0);
            unsigned m3 = __ballot_sync(FULLM, (int)av.w > 0);
            if ((int)av.x > 0) m = fmaxf(m, ev.x);
            if ((int)av.y > 0) m = fmaxf(m, ev.y);
            if ((int)av.z > 0) m = fmaxf(m, ev.z);
            if ((int)av.w > 0) m = fmaxf(m, ev.w);
            if (lane == 0)
                *(uint4*)(mask_sm + lr * 64 + it * 4) = make_uint4(m0, m1, m2, m3);
        }
        #pragma unroll
        for (int off = 16; off; off >>= 1) m = fmaxf(m, __shfl_xor_sync(FULLM, m, off));
        if (lane == 0) {
            const float es = __ldg(g_es + bh * Nn + r) * LOG2E;
            float M, nz;
            if (m < -9e29f) { M = 0.f; nz = 1.f; }   // empty row -> uniform (matches ref)
            else { float s = es + m; M = fmaxf(s, 0.2f * s); nz = 0.f; }
            es_sm[lr] = es; M_sm[lr] = M; nz_sm[lr] = nz;
        }
    }
    __syncthreads();   // masks + row stats ready

    const float esA = es_sm[lrA], MA = M_sm[lrA], nzA = nz_sm[lrA];
    const float esB = es_sm[lrB], MB = M_sm[lrB], nzB = nz_sm[lrB];

    // ---- Pass 2: P (A-fragment layout) @ Wh via mma.m16n8k8 tf32 ----
    float C[4][4];
    #pragma unroll
    for (int nt = 0; nt < 4; nt++)
        #pragma unroll
        for (int k = 0; k < 4; k++) C[nt][k] = 0.f;
    float lA = 0.f, lB = 0.f;

    for (int t = 0; t < NMT; t++) {
        asm volatile("cp.async.wait_group 1;" ::: "memory");
        __syncthreads();   // buf[t&1] ready

        const int jb = t * TJm + par * 32;         // this warp's 32-j slice base
        const int wofs = ((t >> 1) << 2) + qt;     // mask word (128-j granule)
        const unsigned wA = mask_sm[lrA * 64 + wofs];
        const unsigned wB = mask_sm[lrB * 64 + wofs];
        const int bs = (t & 1) * 16 + par * 8;     // bit base within word
        const float* wbuf = wh_sm[t & 1] + par * 32 * WST;

        #pragma unroll
        for (int ks = 0; ks < 4; ks++) {
            const int j0 = ks * 8;
            const float ed0 = ed_sm[jb + j0 + qt];
            const float ed4 = ed_sm[jb + j0 + qt + 4];
            float s;
            s = esA + ed0; s = fmaxf(s, 0.2f * s);
            const float pA0 = ((wA >> (bs + 2 * ks)) & 1u) ? exp2f(s - MA) : nzA;
            s = esB + ed0; s = fmaxf(s, 0.2f * s);
            const float pB0 = ((wB >> (bs + 2 * ks)) & 1u) ? exp2f(s - MB) : nzB;
            s = esA + ed4; s = fmaxf(s, 0.2f * s);
            const float pA4 = ((wA >> (bs + 2 * ks + 1)) & 1u) ? exp2f(s - MA) : nzA;
            s = esB + ed4; s = fmaxf(s, 0.2f * s);
            const float pB4 = ((wB >> (bs + 2 * ks + 1)) & 1u) ? exp2f(s - MB) : nzB;
            lA += pA0 + pA4;
            lB += pB0 + pB4;
            uint32_t a0, a1, a2, a3;
            asm("cvt.rna.tf32.f32 %0, %1;" : "=r"(a0) : "f"(pA0));
            asm("cvt.rna.tf32.f32 %0, %1;" : "=r"(a1) : "f"(pB0));
            asm("cvt.rna.tf32.f32 %0, %1;" : "=r"(a2) : "f"(pA4));
            asm("cvt.rna.tf32.f32 %0, %1;" : "=r"(a3) : "f"(pB4));
            const float* w0p = wbuf + (j0 + qt) * WST + g;
            const float* w1p = wbuf + (j0 + qt + 4) * WST + g;
            #pragma unroll
            for (int nt = 0; nt < 4; nt++) {
                const uint32_t b0 = __float_as_uint(w0p[nt * 8]);
                const uint32_t b1 = __float_as_uint(w1p[nt * 8]);
                asm volatile(
                    "mma.sync.aligned.m16n8k8.row.col.f32.tf32.tf32.f32 "
                    "{%0,%1,%2,%3}, {%4,%5,%6,%7}, {%8,%9}, {%0,%1,%2,%3};"
                    : "+f"(C[nt][0]), "+f"(C[nt][1]), "+f"(C[nt][2]), "+f"(C[nt][3])
                    : "r"(a0), "r"(a1), "r"(a2), "r"(a3), "r"(b0), "r"(b1));
            }
        }

        __syncthreads();   // all warps done with buf[t&1]
        const int nc = t + 2;
        if (nc < NMT) {
            const float* src = whg + (size_t)(nc * TJm) * Dn;
            #pragma unroll
            for (int tt = 0; tt < 2; tt++) {
                int idx = tid + tt * 256;
                int row = idx >> 3, c4 = idx & 7;
                uint32_t dp = (uint32_t)__cvta_generic_to_shared(&wh_sm[nc & 1][row * WST + c4 * 4]);
                asm volatile("cp.async.ca.shared.global [%0], [%1], 16;"
                             :: "r"(dp), "l"(src + row * Dn + c4 * 4));
            }
        }
        asm volatile("cp.async.commit_group;" ::: "memory");   // unconditional
    }

    // ---- Combine the two j-parities (warps w and w+4 hold the same rows) ----
    #pragma unroll
    for (int off = 1; off < 4; off <<= 1) {
        lA += __shfl_xor_sync(FULLM, lA, off);
        lB += __shfl_xor_sync(FULLM, lB, off);
    }

    float* Csc = (float*)mask_sm;          // masks dead after pass 2
    float* lsc = Csc + 64 * CST;
    if (par == 1) {
        #pragma unroll
        for (int nt = 0; nt < 4; nt++) {
            *(float2*)&Csc[lrA * CST + nt * 8 + 2 * qt] = make_float2(C[nt][0], C[nt][1]);
            *(float2*)&Csc[lrB * CST + nt * 8 + 2 * qt] = make_float2(C[nt][2], C[nt][3]);
        }
        if (qt == 0) { lsc[lrA] = lA; lsc[lrB] = lB; }
    }
    __syncthreads();
    if (par == 0) {
        #pragma unroll
        for (int nt = 0; nt < 4; nt++) {
            float2 cA = *(const float2*)&Csc[lrA * CST + nt * 8 + 2 * qt];
            float2 cB = *(const float2*)&Csc[lrB * CST + nt * 8 + 2 * qt];
            C[nt][0] += cA.x; C[nt][1] += cA.y;
            C[nt][2] += cB.x; C[nt][3] += cB.y;
        }
        const float rlA = 1.f / (lA + lsc[lrA]);
        const float rlB = 1.f / (lB + lsc[lrB]);
        const int iA = rbase + lrA;
        const int iB = rbase + lrB;
        float* outA = out + (size_t)(b * Nn + iA) * (Hn * Dn) + hd * Dn + 2 * qt;
        float* outB = out + (size_t)(b * Nn + iB) * (Hn * Dn) + hd * Dn + 2 * qt;
        #pragma unroll
        for (int nt = 0; nt < 4; nt++) {
            *(float2*)(outA + nt * 8) = make_float2(C[nt][0] * rlA, C[nt][1] * rlA);
            *(float2*)(outB + nt * 8) = make_float2(C[nt][2] * rlB, C[nt][3] * rlB);
        }
    }
}

extern "C" void kernel_launch(void* const* d_in, const int* in_sizes, int n_in,
                              void* d_out, int out_size)
{
    // Bind inputs by element count (robust to metadata ordering)
    const float* h = nullptr; const int* adj = nullptr;
    const float* W = nullptr; const float* a = nullptr;
    for (int i = 0; i < n_in; i++) {
        switch (in_sizes[i]) {
            case 1048576: h   = (const float*)d_in[i]; break;
            case 4194304: adj = (const int*)  d_in[i]; break;
            case 16384:   W   = (const float*)d_in[i]; break;
            case 256:     a   = (const float*)d_in[i]; break;
        }
    }
    float* out = (float*)d_out;

    proj_kernel<<<dim3(Bn, Nn / 16), 128>>>(h, W, a);
    attn_kernel<<<dim3(BH, Nn / 64), 256>>>(adj, out);
}

// round 10
// speedup vs baseline: 1.4048x; 1.1302x over previous
#include <cuda_runtime.h>
#include <cuda_fp16.h>
#include <cstdint>

// Problem dims (fixed): B=4, N=2048, F_in=128, H=4, D=32
#define Bn 4
#define Nn 2048
#define Fn 128
#define Hn 4
#define Dn 32
#define BH (Bn*Hn)
#define LOG2E 1.4426950408889634f
#define FULLM 0xffffffffu

// Scratch (device globals; no allocation allowed).
__device__ __align__(256) __half g_WhT[BH * Dn * Nn];  // [bh][d][n] fp16 (transposed) 2 MB
__device__ __align__(16)  float g_es[BH * Nn];         // e_src (exact fp32)
__device__ __align__(16)  float g_ed[BH * Nn];         // e_dst (exact fp32)

// -------------------- Kernel A: projection + e_src/e_dst --------------------
__global__ __launch_bounds__(128) void proj_kernel(
    const float* __restrict__ h, const float* __restrict__ W,
    const float* __restrict__ a)
{
    __shared__ __align__(16) float h_sm[16 * Fn];
    const int b  = blockIdx.x;
    const int n0 = blockIdx.y * 16;

    const float4* hsrc = (const float4*)(h + (size_t)(b * Nn + n0) * Fn);
    float4* hdst = (float4*)h_sm;
    #pragma unroll
    for (int r = 0; r < 4; r++) hdst[threadIdx.x + r * 128] = hsrc[threadIdx.x + r * 128];
    __syncthreads();

    const int warp = threadIdx.x >> 5;   // head
    const int lane = threadIdx.x & 31;   // d

    const float* Wp = W + (warp * Fn) * Dn + lane;
    float acc[16];
    #pragma unroll
    for (int n = 0; n < 16; n++) acc[n] = 0.f;

    #pragma unroll 4
    for (int f = 0; f < Fn; f++) {
        float w = __ldg(Wp + f * Dn);
        #pragma unroll
        for (int n = 0; n < 16; n++)
            acc[n] = fmaf(h_sm[n * Fn + f], w, acc[n]);
    }

    const float a_s = __ldg(a + warp * (2 * Dn) + lane);
    const float a_d = __ldg(a + warp * (2 * Dn) + Dn + lane);

    const int bh = b * Hn + warp;

    // es/ed from EXACT fp32 acc (softmax row-max exactness)
    #pragma unroll
    for (int n = 0; n < 16; n++) {
        float es = acc[n] * a_s;
        float ed = acc[n] * a_d;
        #pragma unroll
        for (int off = 16; off; off >>= 1) {
            es += __shfl_xor_sync(FULLM, es, off);
            ed += __shfl_xor_sync(FULLM, ed, off);
        }
        if (lane == 0) {
            g_es[bh * Nn + n0 + n] = es;
            g_ed[bh * Nn + n0 + n] = ed;
        }
    }

    // store Wh transposed as fp16: [bh][d=lane][n], 32B contiguous per lane
    __align__(16) __half hbuf[16];
    #pragma unroll
    for (int n = 0; n < 16; n++) hbuf[n] = __float2half(acc[n]);
    __half* whp = g_WhT + ((size_t)bh * Dn + lane) * Nn + n0;
    *(uint4*)(whp)     = *(const uint4*)(hbuf);
    *(uint4*)(whp + 8) = *(const uint4*)(hbuf + 8);
}

// -------------------- Kernel B: masked softmax + P@Wh via fp16 MMA --------------------
// Block: 256 threads / 8 warps / 64 rows. Warp w: rows (w&3)*16..+16, j-parity (w>>2).
// mma.m16n8k16 fp16: per k16 step a lane computes p for k in {2qt,2qt+1,2qt+8,2qt+9}
// x rows {g, g+8}; B fragments are fp16 pairs from transposed Wh in smem.
#define TJm 64            // j per meta (two 32-j parity slices)
#define NMT (Nn / TJm)    // 32 metas
#define WSTh 72           // wh_sm row stride (halfs) = 144B -> conflict-free (banks 4g+qt)
#define CST 34            // C-scratch row stride (floats)

__global__ __launch_bounds__(256, 3) void attn_kernel(
    const int* __restrict__ adj, float* __restrict__ out)
{
    __shared__ __align__(16) float    ed_sm[Nn];             // 8 KB (e_dst * LOG2E)
    __shared__ __align__(16) unsigned mask_sm[64 * 64];      // 16 KB adjacency bits (reused as C scratch)
    __shared__ __align__(16) __half   wh_sm[2][32 * WSTh];   // 9 KB double buffer, [d][k] fp16
    __shared__ float es_sm[64], M_sm[64], nz_sm[64];

    const int bh = blockIdx.x;
    const int b  = bh >> 2;
    const int hd = bh & 3;
    const int rbase = blockIdx.y * 64;
    const int tid  = threadIdx.x;
    const int warp = tid >> 5;
    const int lane = tid & 31;
    const int g  = lane >> 2;      // groupID
    const int qt = lane & 3;       // thread-in-group
    const int par = warp >> 2;     // j parity
    const int lrA = (warp & 3) * 16 + g;   // local row A
    const int lrB = lrA + 8;               // local row B

    const __half* whg = g_WhT + (size_t)bh * Dn * Nn;

    // ---- stage e_dst (scaled to log2 units) ----
    {
        const float4* src = (const float4*)(g_ed + bh * Nn);
        float4* dst = (float4*)ed_sm;
        #pragma unroll
        for (int r = 0; r < 2; r++) {
            float4 v = src[tid + r * 256];
            v.x *= LOG2E; v.y *= LOG2E; v.z *= LOG2E; v.w *= LOG2E;
            dst[tid + r * 256] = v;
        }
    }

    // ---- prologue: prefetch WhT metas 0,1 (32 d-rows x 64 k halfs = 4KB each) ----
    #pragma unroll
    for (int c = 0; c < 2; c++) {
        const int row = tid >> 3, c8 = tid & 7;       // 256 threads = 32 rows x 8 x 16B
        uint32_t dp = (uint32_t)__cvta_generic_to_shared(&wh_sm[c][row * WSTh + c8 * 8]);
        asm volatile("cp.async.ca.shared.global [%0], [%1], 16;"
                     :: "r"(dp), "l"((const char*)(whg + (size_t)row * Nn + c * TJm) + c8 * 16));
        asm volatile("cp.async.commit_group;" ::: "memory");
    }

    __syncthreads();   // ed_sm ready

    // ---- Pass 1: pack adjacency bits + exact masked row max (warp scans 8 rows) ----
    // mask word (r, it*4+c) holds bit L for j = it*128 + L*4 + c
    for (int k = 0; k < 8; k++) {
        const int lr = warp * 8 + k;
        const int r  = rbase + lr;
        const int* adjr = adj + (size_t)r * Nn;
        float m = -1e30f;
        #pragma unroll
        for (int it = 0; it < 16; it++) {
            uint4 av = __ldg((const uint4*)(adjr + it * 128 + lane * 4));
            float4 ev = *(const float4*)(ed_sm + it * 128 + lane * 4);
            unsigned m0 = __ballot_sync(FULLM, (int)av.x > 0);
            unsigned m1 = __ballot_sync(FULLM, (int)av.y > 0);
            unsigned m2 = __ballot_sync(FULLM, (int)av.z > 0);
            unsigned m3 = __ballot_sync(FULLM, (int)av.w > 0);
            if ((int)av.x > 0) m = fmaxf(m, ev.x);
            if ((int)av.y > 0) m = fmaxf(m, ev.y);
            if ((int)av.z > 0) m = fmaxf(m, ev.z);
            if ((int)av.w > 0) m = fmaxf(m, ev.w);
            if (lane == 0)
                *(uint4*)(mask_sm + lr * 64 + it * 4) = make_uint4(m0, m1, m2, m3);
        }
        #pragma unroll
        for (int off = 16; off; off >>= 1) m = fmaxf(m, __shfl_xor_sync(FULLM, m, off));
        if (lane == 0) {
            const float es = __ldg(g_es + bh * Nn + r) * LOG2E;
            float M, nz;
            if (m < -9e29f) { M = 0.f; nz = 1.f; }   // empty row -> uniform (matches ref)
            else { float s = es + m; M = fmaxf(s, 0.2f * s); nz = 0.f; }
            es_sm[lr] = es; M_sm[lr] = M; nz_sm[lr] = nz;
        }
    }
    __syncthreads();   // masks + row stats ready

    const float esA = es_sm[lrA], MA = M_sm[lrA], nzA = nz_sm[lrA];
    const float esB = es_sm[lrB], MB = M_sm[lrB], nzB = nz_sm[lrB];

    // ---- Pass 2: P (fp16 A-fragment) @ WhT via mma.m16n8k16 ----
    float C[4][4];
    #pragma unroll
    for (int nt = 0; nt < 4; nt++)
        #pragma unroll
        for (int k = 0; k < 4; k++) C[nt][k] = 0.f;
    float lA = 0.f, lB = 0.f;

    const int c0 = 2 * (qt & 1);     // mask word for even-offset j; c0+1 for odd
    const int hsh = qt >> 1;         // bit sub-offset

    for (int t = 0; t < NMT; t++) {
        asm volatile("cp.async.wait_group 1;" ::: "memory");
        __syncthreads();   // buf[t&1] ready

        const int it = t >> 1;
        const unsigned wA0 = mask_sm[lrA * 64 + (it << 2) + c0];
        const unsigned wA1 = mask_sm[lrA * 64 + (it << 2) + c0 + 1];
        const unsigned wB0 = mask_sm[lrB * 64 + (it << 2) + c0];
        const unsigned wB1 = mask_sm[lrB * 64 + (it << 2) + c0 + 1];
        const int jb = t * TJm + par * 32;
        const int kkb = 4 * (t & 1) + 2 * par;
        const __half* wbuf = wh_sm[t & 1] + par * 32;

        #pragma unroll
        for (int ks = 0; ks < 2; ks++) {
            const int sh = 4 * (kkb + ks) + hsh;
            const int j0 = jb + ks * 16 + 2 * qt;
            const float2 edlo = *(const float2*)(ed_sm + j0);
            const float2 edhi = *(const float2*)(ed_sm + j0 + 8);
            float s;
            s = esA + edlo.x; s = fmaxf(s, 0.2f * s);
            const float pA0 = ((wA0 >> sh) & 1u) ? exp2f(s - MA) : nzA;
            s = esA + edlo.y; s = fmaxf(s, 0.2f * s);
            const float pA1 = ((wA1 >> sh) & 1u) ? exp2f(s - MA) : nzA;
            s = esA + edhi.x; s = fmaxf(s, 0.2f * s);
            const float pA8 = ((wA0 >> (sh + 2)) & 1u) ? exp2f(s - MA) : nzA;
            s = esA + edhi.y; s = fmaxf(s, 0.2f * s);
            const float pA9 = ((wA1 >> (sh + 2)) & 1u) ? exp2f(s - MA) : nzA;
            s = esB + edlo.x; s = fmaxf(s, 0.2f * s);
            const float pB0 = ((wB0 >> sh) & 1u) ? exp2f(s - MB) : nzB;
            s = esB + edlo.y; s = fmaxf(s, 0.2f * s);
            const float pB1 = ((wB1 >> sh) & 1u) ? exp2f(s - MB) : nzB;
            s = esB + edhi.x; s = fmaxf(s, 0.2f * s);
            const float pB8 = ((wB0 >> (sh + 2)) & 1u) ? exp2f(s - MB) : nzB;
            s = esB + edhi.y; s = fmaxf(s, 0.2f * s);
            const float pB9 = ((wB1 >> (sh + 2)) & 1u) ? exp2f(s - MB) : nzB;
            lA += (pA0 + pA1) + (pA8 + pA9);
            lB += (pB0 + pB1) + (pB8 + pB9);
            uint32_t a0, a1, a2, a3;
            asm("cvt.rn.f16x2.f32 %0, %1, %2;" : "=r"(a0) : "f"(pA1), "f"(pA0));
            asm("cvt.rn.f16x2.f32 %0, %1, %2;" : "=r"(a1) : "f"(pB1), "f"(pB0));
            asm("cvt.rn.f16x2.f32 %0, %1, %2;" : "=r"(a2) : "f"(pA9), "f"(pA8));
            asm("cvt.rn.f16x2.f32 %0, %1, %2;" : "=r"(a3) : "f"(pB9), "f"(pB8));
            const __half* bp = wbuf + ks * 16 + 2 * qt;
            #pragma unroll
            for (int nt = 0; nt < 4; nt++) {
                const uint32_t b0 = *(const uint32_t*)(bp + (nt * 8 + g) * WSTh);
                const uint32_t b1 = *(const uint32_t*)(bp + (nt * 8 + g) * WSTh + 8);
                asm volatile(
                    "mma.sync.aligned.m16n8k16.row.col.f32.f16.f16.f32 "
                    "{%0,%1,%2,%3}, {%4,%5,%6,%7}, {%8,%9}, {%0,%1,%2,%3};"
                    : "+f"(C[nt][0]), "+f"(C[nt][1]), "+f"(C[nt][2]), "+f"(C[nt][3])
                    : "r"(a0), "r"(a1), "r"(a2), "r"(a3), "r"(b0), "r"(b1));
            }
        }

        __syncthreads();   // all warps done with buf[t&1]
        const int nc = t + 2;
        if (nc < NMT) {
            const int row = tid >> 3, c8 = tid & 7;
            uint32_t dp = (uint32_t)__cvta_generic_to_shared(&wh_sm[nc & 1][row * WSTh + c8 * 8]);
            asm volatile("cp.async.ca.shared.global [%0], [%1], 16;"
                         :: "r"(dp), "l"((const char*)(whg + (size_t)row * Nn + nc * TJm) + c8 * 16));
        }
        asm volatile("cp.async.commit_group;" ::: "memory");   // unconditional
    }

    // ---- Combine the two j-parities (warps w and w+4 hold the same rows) ----
    #pragma unroll
    for (int off = 1; off < 4; off <<= 1) {
        lA += __shfl_xor_sync(FULLM, lA, off);
        lB += __shfl_xor_sync(FULLM, lB, off);
    }

    float* Csc = (float*)mask_sm;          // masks dead after pass 2
    float* lsc = Csc + 64 * CST;
    if (par == 1) {
        #pragma unroll
        for (int nt = 0; nt < 4; nt++) {
            *(float2*)&Csc[lrA * CST + nt * 8 + 2 * qt] = make_float2(C[nt][0], C[nt][1]);
            *(float2*)&Csc[lrB * CST + nt * 8 + 2 * qt] = make_float2(C[nt][2], C[nt][3]);
        }
        if (qt == 0) { lsc[lrA] = lA; lsc[lrB] = lB; }
    }
    __syncthreads();
    if (par == 0) {
        #pragma unroll
        for (int nt = 0; nt < 4; nt++) {
            float2 cA = *(const float2*)&Csc[lrA * CST + nt * 8 + 2 * qt];
            float2 cB = *(const float2*)&Csc[lrB * CST + nt * 8 + 2 * qt];
            C[nt][0] += cA.x; C[nt][1] += cA.y;
            C[nt][2] += cB.x; C[nt][3] += cB.y;
        }
        const float rlA = 1.f / (lA + lsc[lrA]);
        const float rlB = 1.f / (lB + lsc[lrB]);
        const int iA = rbase + lrA;
        const int iB = rbase + lrB;
        float* outA = out + (size_t)(b * Nn + iA) * (Hn * Dn) + hd * Dn + 2 * qt;
        float* outB = out + (size_t)(b * Nn + iB) * (Hn * Dn) + hd * Dn + 2 * qt;
        #pragma unroll
        for (int nt = 0; nt < 4; nt++) {
            *(float2*)(outA + nt * 8) = make_float2(C[nt][0] * rlA, C[nt][1] * rlA);
            *(float2*)(outB + nt * 8) = make_float2(C[nt][2] * rlB, C[nt][3] * rlB);
        }
    }
}

extern "C" void kernel_launch(void* const* d_in, const int* in_sizes, int n_in,
                              void* d_out, int out_size)
{
    // Bind inputs by element count (robust to metadata ordering)
    const float* h = nullptr; const int* adj = nullptr;
    const float* W = nullptr; const float* a = nullptr;
    for (int i = 0; i < n_in; i++) {
        switch (in_sizes[i]) {
            case 1048576: h   = (const float*)d_in[i]; break;
            case 4194304: adj = (const int*)  d_in[i]; break;
            case 16384:   W   = (const float*)d_in[i]; break;
            case 256:     a   = (const float*)d_in[i]; break;
        }
    }
    float* out = (float*)d_out;

    proj_kernel<<<dim3(Bn, Nn / 16), 128>>>(h, W, a);
    attn_kernel<<<dim3(BH, Nn / 64), 256>>>(adj, out);
}

// round 11
// speedup vs baseline: 1.6534x; 1.1770x over previous
#include <cuda_runtime.h>
#include <cuda_fp16.h>
#include <cstdint>

// Problem dims (fixed): B=4, N=2048, F_in=128, H=4, D=32
#define Bn 4
#define Nn 2048
#define Fn 128
#define Hn 4
#define Dn 32
#define BH (Bn*Hn)
#define LOG2E 1.4426950408889634f
#define FULLM 0xffffffffu

// Scratch (device globals; no allocation allowed).
__device__ __align__(256) __half g_WhT[BH * Dn * Nn];  // [bh][d][n] fp16 (transposed) 2 MB
__device__ __align__(16)  float g_es[BH * Nn];         // e_src (exact fp32)
__device__ __align__(16)  float g_ed[BH * Nn];         // e_dst (exact fp32)

// -------------------- Kernel A: projection + e_src/e_dst --------------------
// 256 threads = 8 warps: warp = (head, n-half). Block does 16 rows.
__global__ __launch_bounds__(256) void proj_kernel(
    const float* __restrict__ h, const float* __restrict__ W,
    const float* __restrict__ a)
{
    __shared__ __align__(16) float h_sm[16 * Fn];
    const int b  = blockIdx.x;
    const int n0 = blockIdx.y * 16;
    const int tid = threadIdx.x;

    const float4* hsrc = (const float4*)(h + (size_t)(b * Nn + n0) * Fn);
    float4* hdst = (float4*)h_sm;
    #pragma unroll
    for (int r = 0; r < 2; r++) hdst[tid + r * 256] = hsrc[tid + r * 256];
    __syncthreads();

    const int warp = tid >> 5;
    const int lane = tid & 31;   // d
    const int hh = warp >> 1;    // head
    const int hf = warp & 1;     // n-half

    const float* Wp = W + (hh * Fn) * Dn + lane;
    float acc[8];
    #pragma unroll
    for (int n = 0; n < 8; n++) acc[n] = 0.f;

    #pragma unroll 4
    for (int f = 0; f < Fn; f++) {
        float w = __ldg(Wp + f * Dn);
        #pragma unroll
        for (int n = 0; n < 8; n++)
            acc[n] = fmaf(h_sm[(hf * 8 + n) * Fn + f], w, acc[n]);
    }

    const float a_s = __ldg(a + hh * (2 * Dn) + lane);
    const float a_d = __ldg(a + hh * (2 * Dn) + Dn + lane);

    const int bh = b * Hn + hh;
    const int nb = n0 + hf * 8;

    // es/ed from EXACT fp32 acc (softmax row-max exactness)
    #pragma unroll
    for (int n = 0; n < 8; n++) {
        float es = acc[n] * a_s;
        float ed = acc[n] * a_d;
        #pragma unroll
        for (int off = 16; off; off >>= 1) {
            es += __shfl_xor_sync(FULLM, es, off);
            ed += __shfl_xor_sync(FULLM, ed, off);
        }
        if (lane == 0) {
            g_es[bh * Nn + nb + n] = es;
            g_ed[bh * Nn + nb + n] = ed;
        }
    }

    // store Wh transposed as fp16: [bh][d=lane][n]
    __align__(16) __half hbuf[8];
    #pragma unroll
    for (int n = 0; n < 8; n++) hbuf[n] = __float2half(acc[n]);
    __half* whp = g_WhT + ((size_t)bh * Dn + lane) * Nn + nb;
    *(uint4*)(whp) = *(const uint4*)(hbuf);
}

// -------------------- Kernel B: masked softmax + P@Wh via fp16 MMA --------------------
// 256 threads / 8 warps / 64 rows. Warp w: rows (w&3)*16..+16, j-half (w>>2) of each
// 128-j meta. mma.m16n8k16 fp16, A = P built in-register, B = WhT from smem.
#define TJm 128           // j per meta (two 64-j halves by parity)
#define NMT (Nn / TJm)    // 16 metas
#define WSTh 136          // wh_sm row stride (halfs) = 272B -> banks 4g+qt, conflict-free
#define CST 34            // C-scratch row stride (floats)

__global__ __launch_bounds__(256, 3) void attn_kernel(
    const int* __restrict__ adj, float* __restrict__ out)
{
    __shared__ __align__(16) float    ed_sm[Nn];             // 8 KB (e_dst * LOG2E)
    __shared__ __align__(16) unsigned mask_sm[64 * 64];      // 16 KB adjacency bits (reused as C scratch)
    __shared__ __align__(16) __half   wh_sm[2][32 * WSTh];   // 17 KB double buffer, [d][k] fp16
    __shared__ float es1_sm[64], es2_sm[64];

    const int bh = blockIdx.x;
    const int b  = bh >> 2;
    const int hd = bh & 3;
    const int rbase = blockIdx.y * 64;
    const int tid  = threadIdx.x;
    const int warp = tid >> 5;
    const int lane = tid & 31;
    const int g  = lane >> 2;      // groupID
    const int qt = lane & 3;       // thread-in-group
    const int par = warp >> 2;     // j half
    const int lrA = (warp & 3) * 16 + g;   // local row A
    const int lrB = lrA + 8;               // local row B

    const __half* whg = g_WhT + (size_t)bh * Dn * Nn;

    // ---- stage e_dst (scaled to log2 units) ----
    {
        const float4* src = (const float4*)(g_ed + bh * Nn);
        float4* dst = (float4*)ed_sm;
        #pragma unroll
        for (int r = 0; r < 2; r++) {
            float4 v = src[tid + r * 256];
            v.x *= LOG2E; v.y *= LOG2E; v.z *= LOG2E; v.w *= LOG2E;
            dst[tid + r * 256] = v;
        }
    }

    // ---- prologue: prefetch WhT metas 0,1 (32 d-rows x 128 k halfs = 8KB each) ----
    #pragma unroll
    for (int c = 0; c < 2; c++) {
        #pragma unroll
        for (int tt = 0; tt < 2; tt++) {
            const int idx = tid + tt * 256;
            const int row = idx >> 4, seg = idx & 15;
            uint32_t dp = (uint32_t)__cvta_generic_to_shared(&wh_sm[c][row * WSTh + seg * 8]);
            asm volatile("cp.async.ca.shared.global [%0], [%1], 16;"
                         :: "r"(dp), "l"(whg + (size_t)row * Nn + c * TJm + seg * 8));
        }
        asm volatile("cp.async.commit_group;" ::: "memory");
    }

    __syncthreads();   // ed_sm ready

    // ---- Pass 1: pack adjacency bits + exact masked row max (warp scans 8 rows) ----
    // mask word (r, it*4+c) holds bit L for j = it*128 + L*4 + c
    for (int k = 0; k < 8; k++) {
        const int lr = warp * 8 + k;
        const int r  = rbase + lr;
        const int* adjr = adj + (size_t)r * Nn;
        float m = -1e30f;
        #pragma unroll
        for (int it = 0; it < 16; it++) {
            uint4 av = __ldg((const uint4*)(adjr + it * 128 + lane * 4));
            float4 ev = *(const float4*)(ed_sm + it * 128 + lane * 4);
            unsigned m0 = __ballot_sync(FULLM, (int)av.x > 0);
            unsigned m1 = __ballot_sync(FULLM, (int)av.y > 0);
            unsigned m2 = __ballot_sync(FULLM, (int)av.z > 0);
            unsigned m3 = __ballot_sync(FULLM, (int)av.w > 0);
            if ((int)av.x > 0) m = fmaxf(m, ev.x);
            if ((int)av.y > 0) m = fmaxf(m, ev.y);
            if ((int)av.z > 0) m = fmaxf(m, ev.z);
            if ((int)av.w > 0) m = fmaxf(m, ev.w);
            if (lane == 0)
                *(uint4*)(mask_sm + lr * 64 + it * 4) = make_uint4(m0, m1, m2, m3);
        }
        #pragma unroll
        for (int off = 16; off; off >>= 1) m = fmaxf(m, __shfl_xor_sync(FULLM, m, off));
        if (lane == 0) {
            const float es = __ldg(g_es + bh * Nn + r) * LOG2E;
            float e1, e2;
            if (m < -9e29f) { e1 = -1e9f; e2 = -1e9f; }   // empty row (impossible) -> p=0, guarded l
            else {
                float s = es + m;
                float M = fmaxf(s, 0.2f * s);
                e1 = es - M;
                e2 = 0.2f * es - M;
            }
            es1_sm[lr] = e1; es2_sm[lr] = e2;
        }
    }
    __syncthreads();   // masks + row stats ready

    const float esA1 = es1_sm[lrA], esA2 = es2_sm[lrA];
    const float esB1 = es1_sm[lrB], esB2 = es2_sm[lrB];

    // ---- Pass 2: P (fp16 A-fragment) @ WhT via mma.m16n8k16 ----
    float C[4][4];
    #pragma unroll
    for (int nt = 0; nt < 4; nt++)
        #pragma unroll
        for (int k = 0; k < 4; k++) C[nt][k] = 0.f;
    float lA = 0.f, lB = 0.f;

    const int c0 = 2 * (qt & 1);     // mask word for even-offset j; c0+1 for odd
    const int hsh = qt >> 1;         // bit sub-offset

    for (int t = 0; t < NMT; t++) {
        asm volatile("cp.async.wait_group 1;" ::: "memory");
        __syncthreads();   // buf[t&1] ready

        const unsigned wA0 = mask_sm[lrA * 64 + (t << 2) + c0];
        const unsigned wA1 = mask_sm[lrA * 64 + (t << 2) + c0 + 1];
        const unsigned wB0 = mask_sm[lrB * 64 + (t << 2) + c0];
        const unsigned wB1 = mask_sm[lrB * 64 + (t << 2) + c0 + 1];
        const int jb = t * TJm + par * 64;
        const __half* wbuf = wh_sm[t & 1] + par * 64;

        #pragma unroll
        for (int ks = 0; ks < 4; ks++) {
            const int sh = par * 16 + ks * 4 + hsh;
            const int j0 = jb + ks * 16 + 2 * qt;
            const float2 edlo = *(const float2*)(ed_sm + j0);
            const float2 edhi = *(const float2*)(ed_sm + j0 + 8);
            float t1, t2, arg;
            t1 = esA1 + edlo.x; t2 = fmaf(0.2f, edlo.x, esA2); arg = fmaxf(t1, t2);
            const float pA0 = ((wA0 >> sh) & 1u) ? exp2f(arg) : 0.f;
            t1 = esA1 + edlo.y; t2 = fmaf(0.2f, edlo.y, esA2); arg = fmaxf(t1, t2);
            const float pA1 = ((wA1 >> sh) & 1u) ? exp2f(arg) : 0.f;
            t1 = esA1 + edhi.x; t2 = fmaf(0.2f, edhi.x, esA2); arg = fmaxf(t1, t2);
            const float pA8 = ((wA0 >> (sh + 2)) & 1u) ? exp2f(arg) : 0.f;
            t1 = esA1 + edhi.y; t2 = fmaf(0.2f, edhi.y, esA2); arg = fmaxf(t1, t2);
            const float pA9 = ((wA1 >> (sh + 2)) & 1u) ? exp2f(arg) : 0.f;
            t1 = esB1 + edlo.x; t2 = fmaf(0.2f, edlo.x, esB2); arg = fmaxf(t1, t2);
            const float pB0 = ((wB0 >> sh) & 1u) ? exp2f(arg) : 0.f;
            t1 = esB1 + edlo.y; t2 = fmaf(0.2f, edlo.y, esB2); arg = fmaxf(t1, t2);
            const float pB1 = ((wB1 >> sh) & 1u) ? exp2f(arg) : 0.f;
            t1 = esB1 + edhi.x; t2 = fmaf(0.2f, edhi.x, esB2); arg = fmaxf(t1, t2);
            const float pB8 = ((wB0 >> (sh + 2)) & 1u) ? exp2f(arg) : 0.f;
            t1 = esB1 + edhi.y; t2 = fmaf(0.2f, edhi.y, esB2); arg = fmaxf(t1, t2);
            const float pB9 = ((wB1 >> (sh + 2)) & 1u) ? exp2f(arg) : 0.f;
            lA += (pA0 + pA1) + (pA8 + pA9);
            lB += (pB0 + pB1) + (pB8 + pB9);
            uint32_t a0, a1, a2, a3;
            asm("cvt.rn.f16x2.f32 %0, %1, %2;" : "=r"(a0) : "f"(pA1), "f"(pA0));
            asm("cvt.rn.f16x2.f32 %0, %1, %2;" : "=r"(a1) : "f"(pB1), "f"(pB0));
            asm("cvt.rn.f16x2.f32 %0, %1, %2;" : "=r"(a2) : "f"(pA9), "f"(pA8));
            asm("cvt.rn.f16x2.f32 %0, %1, %2;" : "=r"(a3) : "f"(pB9), "f"(pB8));
            const __half* bp = wbuf + ks * 16 + 2 * qt;
            #pragma unroll
            for (int nt = 0; nt < 4; nt++) {
                const uint32_t b0 = *(const uint32_t*)(bp + (nt * 8 + g) * WSTh);
                const uint32_t b1 = *(const uint32_t*)(bp + (nt * 8 + g) * WSTh + 8);
                asm volatile(
                    "mma.sync.aligned.m16n8k16.row.col.f32.f16.f16.f32 "
                    "{%0,%1,%2,%3}, {%4,%5,%6,%7}, {%8,%9}, {%0,%1,%2,%3};"
                    : "+f"(C[nt][0]), "+f"(C[nt][1]), "+f"(C[nt][2]), "+f"(C[nt][3])
                    : "r"(a0), "r"(a1), "r"(a2), "r"(a3), "r"(b0), "r"(b1));
            }
        }

        __syncthreads();   // all warps done with buf[t&1]
        const int nc = t + 2;
        if (nc < NMT) {
            #pragma unroll
            for (int tt = 0; tt < 2; tt++) {
                const int idx = tid + tt * 256;
                const int row = idx >> 4, seg = idx & 15;
                uint32_t dp = (uint32_t)__cvta_generic_to_shared(&wh_sm[nc & 1][row * WSTh + seg * 8]);
                asm volatile("cp.async.ca.shared.global [%0], [%1], 16;"
                             :: "r"(dp), "l"(whg + (size_t)row * Nn + nc * TJm + seg * 8));
            }
        }
        asm volatile("cp.async.commit_group;" ::: "memory");   // unconditional
    }

    // ---- Combine the two j-halves (warps w and w+4 hold the same rows) ----
    #pragma unroll
    for (int off = 1; off < 4; off <<= 1) {
        lA += __shfl_xor_sync(FULLM, lA, off);
        lB += __shfl_xor_sync(FULLM, lB, off);
    }

    float* Csc = (float*)mask_sm;          // masks dead after pass 2
    float* lsc = Csc + 64 * CST;
    if (par == 1) {
        #pragma unroll
        for (int nt = 0; nt < 4; nt++) {
            *(float2*)&Csc[lrA * CST + nt * 8 + 2 * qt] = make_float2(C[nt][0], C[nt][1]);
            *(float2*)&Csc[lrB * CST + nt * 8 + 2 * qt] = make_float2(C[nt][2], C[nt][3]);
        }
        if (qt == 0) { lsc[lrA] = lA; lsc[lrB] = lB; }
    }
    __syncthreads();
    if (par == 0) {
        #pragma unroll
        for (int nt = 0; nt < 4; nt++) {
            float2 cA = *(const float2*)&Csc[lrA * CST + nt * 8 + 2 * qt];
            float2 cB = *(const float2*)&Csc[lrB * CST + nt * 8 + 2 * qt];
            C[nt][0] += cA.x; C[nt][1] += cA.y;
            C[nt][2] += cB.x; C[nt][3] += cB.y;
        }
        const float tlA = lA + lsc[lrA];
        const float tlB = lB + lsc[lrB];
        const float rlA = (tlA > 0.f) ? (1.f / tlA) : 0.f;
        const float rlB = (tlB > 0.f) ? (1.f / tlB) : 0.f;
        const int iA = rbase + lrA;
        const int iB = rbase + lrB;
        float* outA = out + (size_t)(b * Nn + iA) * (Hn * Dn) + hd * Dn + 2 * qt;
        float* outB = out + (size_t)(b * Nn + iB) * (Hn * Dn) + hd * Dn + 2 * qt;
        #pragma unroll
        for (int nt = 0; nt < 4; nt++) {
            *(float2*)(outA + nt * 8) = make_float2(C[nt][0] * rlA, C[nt][1] * rlA);
            *(float2*)(outB + nt * 8) = make_float2(C[nt][2] * rlB, C[nt][3] * rlB);
        }
    }
}

extern "C" void kernel_launch(void* const* d_in, const int* in_sizes, int n_in,
                              void* d_out, int out_size)
{
    // Bind inputs by element count (robust to metadata ordering)
    const float* h = nullptr; const int* adj = nullptr;
    const float* W = nullptr; const float* a = nullptr;
    for (int i = 0; i < n_in; i++) {
        switch (in_sizes[i]) {
            case 1048576: h   = (const float*)d_in[i]; break;
            case 4194304: adj = (const int*)  d_in[i]; break;
            case 16384:   W   = (const float*)d_in[i]; break;
            case 256:     a   = (const float*)d_in[i]; break;
        }
    }
    float* out = (float*)d_out;

    proj_kernel<<<dim3(Bn, Nn / 16), 256>>>(h, W, a);
    attn_kernel<<<dim3(BH, Nn / 64), 256>>>(adj, out);
}

// round 12
// speedup vs baseline: 1.7183x; 1.0392x over previous
#include <cuda_runtime.h>
#include <cuda_fp16.h>
#include <cstdint>

// Problem dims (fixed): B=4, N=2048, F_in=128, H=4, D=32
#define Bn 4
#define Nn 2048
#define Fn 128
#define Hn 4
#define Dn 32
#define BH (Bn*Hn)
#define LOG2E 1.4426950408889634f
#define FULLM 0xffffffffu

__device__ __forceinline__ float ex2(float x) {
    float r; asm("ex2.approx.f32 %0, %1;" : "=f"(r) : "f"(x)); return r;
}

// Scratch (device globals; no allocation allowed).
__device__ __align__(256) __half g_WhT[BH * Dn * Nn];  // [bh][d][n] fp16 (transposed) 2 MB
__device__ __align__(16)  float g_es[BH * Nn];         // e_src (exact fp32)
__device__ __align__(16)  float g_ed[BH * Nn];         // e_dst (exact fp32)

// -------------------- Kernel A: projection + e_src/e_dst --------------------
// 256 threads = 8 warps: warp = (head, n-half). Block does 16 rows.
__global__ __launch_bounds__(256) void proj_kernel(
    const float* __restrict__ h, const float* __restrict__ W,
    const float* __restrict__ a)
{
    __shared__ __align__(16) float h_sm[16 * Fn];
    const int b  = blockIdx.x;
    const int n0 = blockIdx.y * 16;
    const int tid = threadIdx.x;

    const float4* hsrc = (const float4*)(h + (size_t)(b * Nn + n0) * Fn);
    float4* hdst = (float4*)h_sm;
    #pragma unroll
    for (int r = 0; r < 2; r++) hdst[tid + r * 256] = hsrc[tid + r * 256];
    __syncthreads();

    const int warp = tid >> 5;
    const int lane = tid & 31;   // d
    const int hh = warp >> 1;    // head
    const int hf = warp & 1;     // n-half

    const float* Wp = W + (hh * Fn) * Dn + lane;
    float acc[8];
    #pragma unroll
    for (int n = 0; n < 8; n++) acc[n] = 0.f;

    #pragma unroll 4
    for (int f4 = 0; f4 < Fn / 4; f4++) {
        const float w0 = __ldg(Wp + (4 * f4 + 0) * Dn);
        const float w1 = __ldg(Wp + (4 * f4 + 1) * Dn);
        const float w2 = __ldg(Wp + (4 * f4 + 2) * Dn);
        const float w3 = __ldg(Wp + (4 * f4 + 3) * Dn);
        #pragma unroll
        for (int n = 0; n < 8; n++) {
            const float4 hv = *(const float4*)(h_sm + (hf * 8 + n) * Fn + 4 * f4);
            acc[n] = fmaf(hv.x, w0, acc[n]);
            acc[n] = fmaf(hv.y, w1, acc[n]);
            acc[n] = fmaf(hv.z, w2, acc[n]);
            acc[n] = fmaf(hv.w, w3, acc[n]);
        }
    }

    const float a_s = __ldg(a + hh * (2 * Dn) + lane);
    const float a_d = __ldg(a + hh * (2 * Dn) + Dn + lane);

    const int bh = b * Hn + hh;
    const int nb = n0 + hf * 8;

    // es/ed from EXACT fp32 acc (softmax row-max exactness)
    #pragma unroll
    for (int n = 0; n < 8; n++) {
        float es = acc[n] * a_s;
        float ed = acc[n] * a_d;
        #pragma unroll
        for (int off = 16; off; off >>= 1) {
            es += __shfl_xor_sync(FULLM, es, off);
            ed += __shfl_xor_sync(FULLM, ed, off);
        }
        if (lane == 0) {
            g_es[bh * Nn + nb + n] = es;
            g_ed[bh * Nn + nb + n] = ed;
        }
    }

    // store Wh transposed as fp16: [bh][d=lane][n]
    __align__(16) __half hbuf[8];
    #pragma unroll
    for (int n = 0; n < 8; n++) hbuf[n] = __float2half(acc[n]);
    __half* whp = g_WhT + ((size_t)bh * Dn + lane) * Nn + nb;
    *(uint4*)(whp) = *(const uint4*)(hbuf);
}

// -------------------- Kernel B: masked softmax + P@Wh via fp16 MMA --------------------
// 256 threads / 8 warps / 64 rows. Warp w: rows (w&3)*16..+16, j-half (w>>2) of each
// 128-j meta. mma.m16n8k16 fp16; 5th n-tile has a ones-column -> C[4] col0 = row sum l.
#define TJm 128           // j per meta (two 64-j halves by parity)
#define NMT (Nn / TJm)    // 16 metas
#define WSTh 136          // wh_sm row stride (halfs) = 272B -> conflict-free
#define CST 34            // C-scratch row stride (floats)

__global__ __launch_bounds__(256, 3) void attn_kernel(
    const int* __restrict__ adj, float* __restrict__ out)
{
    __shared__ __align__(16) float    ed_sm[Nn];             // 8 KB (e_dst * LOG2E)
    __shared__ __align__(16) unsigned mask_sm[64 * 64];      // 16 KB adjacency bits (reused as C scratch)
    __shared__ __align__(16) __half   wh_sm[2][40 * WSTh];   // 21.3 KB: rows 0-31 Wh, 32 ones, 33-39 zero
    __shared__ float es1_sm[64], es2_sm[64];

    const int bh = blockIdx.x;
    const int b  = bh >> 2;
    const int hd = bh & 3;
    const int rbase = blockIdx.y * 64;
    const int tid  = threadIdx.x;
    const int warp = tid >> 5;
    const int lane = tid & 31;
    const int g  = lane >> 2;      // groupID
    const int qt = lane & 3;       // thread-in-group
    const int par = warp >> 2;     // j half
    const int lrA = (warp & 3) * 16 + g;   // local row A
    const int lrB = lrA + 8;               // local row B

    const __half* whg = g_WhT + (size_t)bh * Dn * Nn;

    // ---- stage e_dst (scaled to log2 units) ----
    {
        const float4* src = (const float4*)(g_ed + bh * Nn);
        float4* dst = (float4*)ed_sm;
        #pragma unroll
        for (int r = 0; r < 2; r++) {
            float4 v = src[tid + r * 256];
            v.x *= LOG2E; v.y *= LOG2E; v.z *= LOG2E; v.w *= LOG2E;
            dst[tid + r * 256] = v;
        }
    }

    // ---- fill constant rows 32-39 (ones column for l) of both buffers ----
    for (int i = tid; i < 2 * 8 * WSTh; i += 256) {
        const int buf = i / (8 * WSTh);
        const int rem = i % (8 * WSTh);
        const int row = 32 + rem / WSTh;
        wh_sm[buf][row * WSTh + (rem % WSTh)] = (row == 32) ? __float2half(1.f) : __float2half(0.f);
    }

    // ---- prologue: prefetch WhT metas 0,1 (32 d-rows x 128 k halfs = 8KB each) ----
    #pragma unroll
    for (int c = 0; c < 2; c++) {
        #pragma unroll
        for (int tt = 0; tt < 2; tt++) {
            const int idx = tid + tt * 256;
            const int row = idx >> 4, seg = idx & 15;
            uint32_t dp = (uint32_t)__cvta_generic_to_shared(&wh_sm[c][row * WSTh + seg * 8]);
            asm volatile("cp.async.ca.shared.global [%0], [%1], 16;"
                         :: "r"(dp), "l"(whg + (size_t)row * Nn + c * TJm + seg * 8));
        }
        asm volatile("cp.async.commit_group;" ::: "memory");
    }

    __syncthreads();   // ed_sm ready

    // ---- Pass 1: pack adjacency bits + exact masked row max (warp scans 8 rows) ----
    // mask word (r, it*4+c) holds bit L for j = it*128 + L*4 + c
    for (int k = 0; k < 8; k++) {
        const int lr = warp * 8 + k;
        const int r  = rbase + lr;
        const int* adjr = adj + (size_t)r * Nn;
        float m = -1e30f;
        #pragma unroll
        for (int it = 0; it < 16; it++) {
            uint4 av = __ldg((const uint4*)(adjr + it * 128 + lane * 4));
            float4 ev = *(const float4*)(ed_sm + it * 128 + lane * 4);
            unsigned m0 = __ballot_sync(FULLM, (int)av.x > 0);
            unsigned m1 = __ballot_sync(FULLM, (int)av.y > 0);
            unsigned m2 = __ballot_sync(FULLM, (int)av.z > 0);
            unsigned m3 = __ballot_sync(FULLM, (int)av.w > 0);
            if ((int)av.x > 0) m = fmaxf(m, ev.x);
            if ((int)av.y > 0) m = fmaxf(m, ev.y);
            if ((int)av.z > 0) m = fmaxf(m, ev.z);
            if ((int)av.w > 0) m = fmaxf(m, ev.w);
            if (lane == 0)
                *(uint4*)(mask_sm + lr * 64 + it * 4) = make_uint4(m0, m1, m2, m3);
        }
        #pragma unroll
        for (int off = 16; off; off >>= 1) m = fmaxf(m, __shfl_xor_sync(FULLM, m, off));
        if (lane == 0) {
            const float es = __ldg(g_es + bh * Nn + r) * LOG2E;
            float e1, e2;
            if (m < -9e29f) { e1 = -1e9f; e2 = -1e9f; }   // empty row -> all p=0, guarded l
            else {
                float s = es + m;
                float M = fmaxf(s, 0.2f * s);
                e1 = es - M;
                e2 = 0.2f * es - M;
            }
            es1_sm[lr] = e1; es2_sm[lr] = e2;
        }
    }
    __syncthreads();   // masks + row stats ready

    const float esA1 = es1_sm[lrA], esA2 = es2_sm[lrA];
    const float esB1 = es1_sm[lrB], esB2 = es2_sm[lrB];

    // ---- Pass 2: P (fp16 A-fragment) @ WhT via mma.m16n8k16; tile 4 yields l ----
    float C[5][4];
    #pragma unroll
    for (int nt = 0; nt < 5; nt++)
        #pragma unroll
        for (int k = 0; k < 4; k++) C[nt][k] = 0.f;

    const int c0 = 2 * (qt & 1);     // mask word for even-offset j; c0+1 for odd
    const int psh = par * 16 + (qt >> 1);   // hoisted shift base

    for (int t = 0; t < NMT; t++) {
        asm volatile("cp.async.wait_group 1;" ::: "memory");
        __syncthreads();   // buf[t&1] ready

        const unsigned wA0 = mask_sm[lrA * 64 + (t << 2) + c0]     >> psh;
        const unsigned wA1 = mask_sm[lrA * 64 + (t << 2) + c0 + 1] >> psh;
        const unsigned wB0 = mask_sm[lrB * 64 + (t << 2) + c0]     >> psh;
        const unsigned wB1 = mask_sm[lrB * 64 + (t << 2) + c0 + 1] >> psh;
        const int jb = t * TJm + par * 64;
        const __half* wbuf = wh_sm[t & 1] + par * 64;

        #pragma unroll
        for (int ks = 0; ks < 4; ks++) {
            const int j0 = jb + ks * 16 + 2 * qt;
            const float2 edlo = *(const float2*)(ed_sm + j0);
            const float2 edhi = *(const float2*)(ed_sm + j0 + 8);
            float t1, t2;
            t1 = esA1 + edlo.x; t2 = fmaf(0.2f, edlo.x, esA2);
            const float pA0 = (wA0 & (1u << (4 * ks)))       ? ex2(fmaxf(t1, t2)) : 0.f;
            t1 = esA1 + edlo.y; t2 = fmaf(0.2f, edlo.y, esA2);
            const float pA1 = (wA1 & (1u << (4 * ks)))       ? ex2(fmaxf(t1, t2)) : 0.f;
            t1 = esA1 + edhi.x; t2 = fmaf(0.2f, edhi.x, esA2);
            const float pA8 = (wA0 & (1u << (4 * ks + 2)))   ? ex2(fmaxf(t1, t2)) : 0.f;
            t1 = esA1 + edhi.y; t2 = fmaf(0.2f, edhi.y, esA2);
            const float pA9 = (wA1 & (1u << (4 * ks + 2)))   ? ex2(fmaxf(t1, t2)) : 0.f;
            t1 = esB1 + edlo.x; t2 = fmaf(0.2f, edlo.x, esB2);
            const float pB0 = (wB0 & (1u << (4 * ks)))       ? ex2(fmaxf(t1, t2)) : 0.f;
            t1 = esB1 + edlo.y; t2 = fmaf(0.2f, edlo.y, esB2);
            const float pB1 = (wB1 & (1u << (4 * ks)))       ? ex2(fmaxf(t1, t2)) : 0.f;
            t1 = esB1 + edhi.x; t2 = fmaf(0.2f, edhi.x, esB2);
            const float pB8 = (wB0 & (1u << (4 * ks + 2)))   ? ex2(fmaxf(t1, t2)) : 0.f;
            t1 = esB1 + edhi.y; t2 = fmaf(0.2f, edhi.y, esB2);
            const float pB9 = (wB1 & (1u << (4 * ks + 2)))   ? ex2(fmaxf(t1, t2)) : 0.f;
            uint32_t a0, a1, a2, a3;
            asm("cvt.rn.f16x2.f32 %0, %1, %2;" : "=r"(a0) : "f"(pA1), "f"(pA0));
            asm("cvt.rn.f16x2.f32 %0, %1, %2;" : "=r"(a1) : "f"(pB1), "f"(pB0));
            asm("cvt.rn.f16x2.f32 %0, %1, %2;" : "=r"(a2) : "f"(pA9), "f"(pA8));
            asm("cvt.rn.f16x2.f32 %0, %1, %2;" : "=r"(a3) : "f"(pB9), "f"(pB8));
            const __half* bp = wbuf + ks * 16 + 2 * qt;
            #pragma unroll
            for (int nt = 0; nt < 5; nt++) {
                const uint32_t b0 = *(const uint32_t*)(bp + (nt * 8 + g) * WSTh);
                const uint32_t b1 = *(const uint32_t*)(bp + (nt * 8 + g) * WSTh + 8);
                asm volatile(
                    "mma.sync.aligned.m16n8k16.row.col.f32.f16.f16.f32 "
                    "{%0,%1,%2,%3}, {%4,%5,%6,%7}, {%8,%9}, {%0,%1,%2,%3};"
                    : "+f"(C[nt][0]), "+f"(C[nt][1]), "+f"(C[nt][2]), "+f"(C[nt][3])
                    : "r"(a0), "r"(a1), "r"(a2), "r"(a3), "r"(b0), "r"(b1));
            }
        }

        __syncthreads();   // all warps done with buf[t&1]
        const int nc = t + 2;
        if (nc < NMT) {
            #pragma unroll
            for (int tt = 0; tt < 2; tt++) {
                const int idx = tid + tt * 256;
                const int row = idx >> 4, seg = idx & 15;
                uint32_t dp = (uint32_t)__cvta_generic_to_shared(&wh_sm[nc & 1][row * WSTh + seg * 8]);
                asm volatile("cp.async.ca.shared.global [%0], [%1], 16;"
                             :: "r"(dp), "l"(whg + (size_t)row * Nn + nc * TJm + seg * 8));
            }
        }
        asm volatile("cp.async.commit_group;" ::: "memory");   // unconditional
    }

    // l from the ones-column (tile 4, col 0): qt=0 lanes hold it; broadcast in quad.
    const float lA = __shfl_sync(FULLM, C[4][0], lane & ~3);
    const float lB = __shfl_sync(FULLM, C[4][2], lane & ~3);

    // ---- Combine the two j-halves (warps w and w+4 hold the same rows) ----
    float* Csc = (float*)mask_sm;          // masks dead after pass 2
    float* lsc = Csc + 64 * CST;
    if (par == 1) {
        #pragma unroll
        for (int nt = 0; nt < 4; nt++) {
            *(float2*)&Csc[lrA * CST + nt * 8 + 2 * qt] = make_float2(C[nt][0], C[nt][1]);
            *(float2*)&Csc[lrB * CST + nt * 8 + 2 * qt] = make_float2(C[nt][2], C[nt][3]);
        }
        if (qt == 0) { lsc[lrA] = lA; lsc[lrB] = lB; }
    }
    __syncthreads();
    if (par == 0) {
        #pragma unroll
        for (int nt = 0; nt < 4; nt++) {
            float2 cA = *(const float2*)&Csc[lrA * CST + nt * 8 + 2 * qt];
            float2 cB = *(const float2*)&Csc[lrB * CST + nt * 8 + 2 * qt];
            C[nt][0] += cA.x; C[nt][1] += cA.y;
            C[nt][2] += cB.x; C[nt][3] += cB.y;
        }
        const float tlA = lA + lsc[lrA];
        const float tlB = lB + lsc[lrB];
        const float rlA = (tlA > 0.f) ? (1.f / tlA) : 0.f;
        const float rlB = (tlB > 0.f) ? (1.f / tlB) : 0.f;
        const int iA = rbase + lrA;
        const int iB = rbase + lrB;
        float* outA = out + (size_t)(b * Nn + iA) * (Hn * Dn) + hd * Dn + 2 * qt;
        float* outB = out + (size_t)(b * Nn + iB) * (Hn * Dn) + hd * Dn + 2 * qt;
        #pragma unroll
        for (int nt = 0; nt < 4; nt++) {
            *(float2*)(outA + nt * 8) = make_float2(C[nt][0] * rlA, C[nt][1] * rlA);
            *(float2*)(outB + nt * 8) = make_float2(C[nt][2] * rlB, C[nt][3] * rlB);
        }
    }
}

extern "C" void kernel_launch(void* const* d_in, const int* in_sizes, int n_in,
                              void* d_out, int out_size)
{
    // Bind inputs by element count (robust to metadata ordering)
    const float* h = nullptr; const int* adj = nullptr;
    const float* W = nullptr; const float* a = nullptr;
    for (int i = 0; i < n_in; i++) {
        switch (in_sizes[i]) {
            case 1048576: h   = (const float*)d_in[i]; break;
            case 4194304: adj = (const int*)  d_in[i]; break;
            case 16384:   W   = (const float*)d_in[i]; break;
            case 256:     a   = (const float*)d_in[i]; break;
        }
    }
    float* out = (float*)d_out;

    proj_kernel<<<dim3(Bn, Nn / 16), 256>>>(h, W, a);
    attn_kernel<<<dim3(BH, Nn / 64), 256>>>(adj, out);
}

// round 13
// speedup vs baseline: 1.7486x; 1.0177x over previous
#include <cuda_runtime.h>
#include <cuda_fp16.h>
#include <cstdint>

// Problem dims (fixed): B=4, N=2048, F_in=128, H=4, D=32
#define Bn 4
#define Nn 2048
#define Fn 128
#define Hn 4
#define Dn 32
#define BH (Bn*Hn)
#define LOG2E 1.4426950408889634f
#define FULLM 0xffffffffu

__device__ __forceinline__ float ex2(float x) {
    float r; asm("ex2.approx.f32 %0, %1;" : "=f"(r) : "f"(x)); return r;
}

// Scratch (device globals; no allocation allowed).
// g_WhT layout: [bh][d][n'] fp16 where n' permutes n within each 16-group:
// positions [0,1,8,9,2,3,10,11,4,5,12,13,6,7,14,15] -> true n. This makes the
// 4 B-fragment halfs of a quad-thread contiguous (one LDS.64 in attn).
__device__ __align__(256) __half g_WhT[BH * Dn * Nn];
__device__ __align__(16)  float g_es[BH * Nn];         // e_src (exact fp32)
__device__ __align__(16)  float g_ed[BH * Nn];         // e_dst (exact fp32)

// -------------------- Kernel A: projection + e_src/e_dst --------------------
// 256 threads = 8 warps: warp = (head, n-half). Block does 16 rows.
__global__ __launch_bounds__(256) void proj_kernel(
    const float* __restrict__ h, const float* __restrict__ W,
    const float* __restrict__ a)
{
    __shared__ __align__(16) float h_sm[16 * Fn];
    const int b  = blockIdx.x;
    const int n0 = blockIdx.y * 16;
    const int tid = threadIdx.x;

    const float4* hsrc = (const float4*)(h + (size_t)(b * Nn + n0) * Fn);
    float4* hdst = (float4*)h_sm;
    #pragma unroll
    for (int r = 0; r < 2; r++) hdst[tid + r * 256] = hsrc[tid + r * 256];
    __syncthreads();

    const int warp = tid >> 5;
    const int lane = tid & 31;   // d
    const int hh = warp >> 1;    // head
    const int hf = warp & 1;     // n-half

    const float* Wp = W + (hh * Fn) * Dn + lane;
    float acc[8];
    #pragma unroll
    for (int n = 0; n < 8; n++) acc[n] = 0.f;

    #pragma unroll 4
    for (int f4 = 0; f4 < Fn / 4; f4++) {
        const float w0 = __ldg(Wp + (4 * f4 + 0) * Dn);
        const float w1 = __ldg(Wp + (4 * f4 + 1) * Dn);
        const float w2 = __ldg(Wp + (4 * f4 + 2) * Dn);
        const float w3 = __ldg(Wp + (4 * f4 + 3) * Dn);
        #pragma unroll
        for (int n = 0; n < 8; n++) {
            const float4 hv = *(const float4*)(h_sm + (hf * 8 + n) * Fn + 4 * f4);
            acc[n] = fmaf(hv.x, w0, acc[n]);
            acc[n] = fmaf(hv.y, w1, acc[n]);
            acc[n] = fmaf(hv.z, w2, acc[n]);
            acc[n] = fmaf(hv.w, w3, acc[n]);
        }
    }

    const float a_s = __ldg(a + hh * (2 * Dn) + lane);
    const float a_d = __ldg(a + hh * (2 * Dn) + Dn + lane);

    const int bh = b * Hn + hh;

    // es/ed from EXACT fp32 acc (softmax row-max exactness)
    #pragma unroll
    for (int n = 0; n < 8; n++) {
        float es = acc[n] * a_s;
        float ed = acc[n] * a_d;
        #pragma unroll
        for (int off = 16; off; off >>= 1) {
            es += __shfl_xor_sync(FULLM, es, off);
            ed += __shfl_xor_sync(FULLM, ed, off);
        }
        if (lane == 0) {
            g_es[bh * Nn + n0 + hf * 8 + n] = es;
            g_ed[bh * Nn + n0 + hf * 8 + n] = ed;
        }
    }

    // store Wh transposed fp16 with within-16 k-permutation:
    // true t = hf*8 + 2q+e  -> half position 4q + 2*hf + e
    uint32_t* wp32 = (uint32_t*)(g_WhT + ((size_t)bh * Dn + lane) * Nn + n0);
    #pragma unroll
    for (int q = 0; q < 4; q++) {
        uint32_t pk;
        asm("cvt.rn.f16x2.f32 %0, %1, %2;" : "=r"(pk) : "f"(acc[2 * q + 1]), "f"(acc[2 * q]));
        wp32[2 * q + hf] = pk;
    }
}

// -------------------- Kernel B: masked softmax + P@Wh via fp16 MMA --------------------
// 256 threads / 8 warps / 64 rows. Warp w: rows (w&3)*16..+16, j-half (w>>2) of each
// 128-j meta. mma.m16n8k16 fp16; 5th n-tile (ones column, shared const) yields l.
#define TJm 128           // j per meta (two 64-j halves by parity)
#define NMT (Nn / TJm)    // 16 metas
#define WSTh 144          // wh_sm row stride (halfs) = 288B -> LDS.64 conflict-free
#define CST 34            // C-scratch row stride (floats)

__global__ __launch_bounds__(256, 3) void attn_kernel(
    const int* __restrict__ adj, float* __restrict__ out)
{
    __shared__ __align__(16) float    ed_sm[Nn];             // 8 KB (e_dst * LOG2E)
    __shared__ __align__(16) unsigned mask_sm[64 * 64];      // 16 KB adjacency bits (reused as C scratch)
    __shared__ __align__(16) __half   wh_sm[2][32 * WSTh];   // 18 KB double buffer, [d][k'] fp16
    __shared__ __align__(16) __half   cones[8 * WSTh];       // 2.3 KB: row 0 = ones (l), rows 1-7 zero
    __shared__ float es1_sm[64], es2_sm[64];

    const int bh = blockIdx.x;
    const int b  = bh >> 2;
    const int hd = bh & 3;
    const int rbase = blockIdx.y * 64;
    const int tid  = threadIdx.x;
    const int warp = tid >> 5;
    const int lane = tid & 31;
    const int g  = lane >> 2;      // groupID
    const int qt = lane & 3;       // thread-in-group
    const int par = warp >> 2;     // j half
    const int lrA = (warp & 3) * 16 + g;   // local row A
    const int lrB = lrA + 8;               // local row B

    const __half* whg = g_WhT + (size_t)bh * Dn * Nn;

    // ---- stage e_dst (scaled to log2 units) ----
    {
        const float4* src = (const float4*)(g_ed + bh * Nn);
        float4* dst = (float4*)ed_sm;
        #pragma unroll
        for (int r = 0; r < 2; r++) {
            float4 v = src[tid + r * 256];
            v.x *= LOG2E; v.y *= LOG2E; v.z *= LOG2E; v.w *= LOG2E;
            dst[tid + r * 256] = v;
        }
    }

    // ---- fill constant tile: row 0 ones, rows 1-7 zero ----
    for (int i = tid; i < 8 * WSTh; i += 256)
        cones[i] = (i < WSTh) ? __float2half(1.f) : __float2half(0.f);

    // ---- prologue: prefetch WhT metas 0,1 (32 d-rows x 128 k halfs = 8KB each) ----
    #pragma unroll
    for (int c = 0; c < 2; c++) {
        #pragma unroll
        for (int tt = 0; tt < 2; tt++) {
            const int idx = tid + tt * 256;
            const int row = idx >> 4, seg = idx & 15;
            uint32_t dp = (uint32_t)__cvta_generic_to_shared(&wh_sm[c][row * WSTh + seg * 8]);
            asm volatile("cp.async.ca.shared.global [%0], [%1], 16;"
                         :: "r"(dp), "l"(whg + (size_t)row * Nn + c * TJm + seg * 8));
        }
        asm volatile("cp.async.commit_group;" ::: "memory");
    }

    __syncthreads();   // ed_sm ready

    // ---- Pass 1: pack adjacency bits + exact masked row max (warp scans 8 rows) ----
    // mask word (r, it*4+c) holds bit L for j = it*128 + L*4 + c
    for (int k = 0; k < 8; k++) {
        const int lr = warp * 8 + k;
        const int r  = rbase + lr;
        const int* adjr = adj + (size_t)r * Nn;
        float m = -1e30f;
        #pragma unroll
        for (int it = 0; it < 16; it++) {
            uint4 av = __ldg((const uint4*)(adjr + it * 128 + lane * 4));
            float4 ev = *(const float4*)(ed_sm + it * 128 + lane * 4);
            unsigned m0 = __ballot_sync(FULLM, (int)av.x > 0);
            unsigned m1 = __ballot_sync(FULLM, (int)av.y > 0);
            unsigned m2 = __ballot_sync(FULLM, (int)av.z > 0);
            unsigned m3 = __ballot_sync(FULLM, (int)av.w > 0);
            if ((int)av.x > 0) m = fmaxf(m, ev.x);
            if ((int)av.y > 0) m = fmaxf(m, ev.y);
            if ((int)av.z > 0) m = fmaxf(m, ev.z);
            if ((int)av.w > 0) m = fmaxf(m, ev.w);
            if (lane == 0)
                *(uint4*)(mask_sm + lr * 64 + it * 4) = make_uint4(m0, m1, m2, m3);
        }
        #pragma unroll
        for (int off = 16; off; off >>= 1) m = fmaxf(m, __shfl_xor_sync(FULLM, m, off));
        if (lane == 0) {
            const float es = __ldg(g_es + bh * Nn + r) * LOG2E;
            float e1, e2;
            if (m < -9e29f) { e1 = -1e9f; e2 = -1e9f; }   // empty row -> all p=0, guarded l
            else {
                float s = es + m;
                float M = fmaxf(s, 0.2f * s);
                e1 = es - M;
                e2 = 0.2f * es - M;
            }
            es1_sm[lr] = e1; es2_sm[lr] = e2;
        }
    }
    __syncthreads();   // masks + row stats ready

    const float esA1 = es1_sm[lrA], esA2 = es2_sm[lrA];
    const float esB1 = es1_sm[lrB], esB2 = es2_sm[lrB];

    // ---- Pass 2: P (fp16 A-fragment) @ WhT via mma.m16n8k16; tile 4 yields l ----
    float C[5][4];
    #pragma unroll
    for (int nt = 0; nt < 5; nt++)
        #pragma unroll
        for (int k = 0; k < 4; k++) C[nt][k] = 0.f;

    const int c0 = 2 * (qt & 1);     // mask word pair base
    const int psh = par * 16 + (qt >> 1);   // hoisted shift base

    for (int t = 0; t < NMT; t++) {
        asm volatile("cp.async.wait_group 1;" ::: "memory");
        __syncthreads();   // buf[t&1] ready

        const uint2 mwA = *(const uint2*)&mask_sm[lrA * 64 + (t << 2) + c0];
        const uint2 mwB = *(const uint2*)&mask_sm[lrB * 64 + (t << 2) + c0];
        const unsigned wA0 = mwA.x >> psh;
        const unsigned wA1 = mwA.y >> psh;
        const unsigned wB0 = mwB.x >> psh;
        const unsigned wB1 = mwB.y >> psh;
        const int jb = t * TJm + par * 64;
        const __half* wbuf = wh_sm[t & 1] + par * 64;

        #pragma unroll
        for (int ks = 0; ks < 4; ks++) {
            const int j0 = jb + ks * 16 + 2 * qt;
            const float2 edlo = *(const float2*)(ed_sm + j0);
            const float2 edhi = *(const float2*)(ed_sm + j0 + 8);
            float t1, t2;
            float pA0 = 0.f, pA1 = 0.f, pA8 = 0.f, pA9 = 0.f;
            float pB0 = 0.f, pB1 = 0.f, pB8 = 0.f, pB9 = 0.f;
            t1 = esA1 + edlo.x; t2 = fmaf(0.2f, edlo.x, esA2);
            if (wA0 & (1u << (4 * ks)))     pA0 = ex2(fmaxf(t1, t2));
            t1 = esA1 + edlo.y; t2 = fmaf(0.2f, edlo.y, esA2);
            if (wA1 & (1u << (4 * ks)))     pA1 = ex2(fmaxf(t1, t2));
            t1 = esA1 + edhi.x; t2 = fmaf(0.2f, edhi.x, esA2);
            if (wA0 & (1u << (4 * ks + 2))) pA8 = ex2(fmaxf(t1, t2));
            t1 = esA1 + edhi.y; t2 = fmaf(0.2f, edhi.y, esA2);
            if (wA1 & (1u << (4 * ks + 2))) pA9 = ex2(fmaxf(t1, t2));
            t1 = esB1 + edlo.x; t2 = fmaf(0.2f, edlo.x, esB2);
            if (wB0 & (1u << (4 * ks)))     pB0 = ex2(fmaxf(t1, t2));
            t1 = esB1 + edlo.y; t2 = fmaf(0.2f, edlo.y, esB2);
            if (wB1 & (1u << (4 * ks)))     pB1 = ex2(fmaxf(t1, t2));
            t1 = esB1 + edhi.x; t2 = fmaf(0.2f, edhi.x, esB2);
            if (wB0 & (1u << (4 * ks + 2))) pB8 = ex2(fmaxf(t1, t2));
            t1 = esB1 + edhi.y; t2 = fmaf(0.2f, edhi.y, esB2);
            if (wB1 & (1u << (4 * ks + 2))) pB9 = ex2(fmaxf(t1, t2));
            uint32_t a0, a1, a2, a3;
            asm("cvt.rn.f16x2.f32 %0, %1, %2;" : "=r"(a0) : "f"(pA1), "f"(pA0));
            asm("cvt.rn.f16x2.f32 %0, %1, %2;" : "=r"(a1) : "f"(pB1), "f"(pB0));
            asm("cvt.rn.f16x2.f32 %0, %1, %2;" : "=r"(a2) : "f"(pA9), "f"(pA8));
            asm("cvt.rn.f16x2.f32 %0, %1, %2;" : "=r"(a3) : "f"(pB9), "f"(pB8));
            // B fragments: permuted layout -> one LDS.64 per tile
            const __half* bpt = wbuf + ks * 16 + 4 * qt;
            #pragma unroll
            for (int nt = 0; nt < 4; nt++) {
                const uint2 bb = *(const uint2*)(bpt + (nt * 8 + g) * WSTh);
                asm volatile(
                    "mma.sync.aligned.m16n8k16.row.col.f32.f16.f16.f32 "
                    "{%0,%1,%2,%3}, {%4,%5,%6,%7}, {%8,%9}, {%0,%1,%2,%3};"
                    : "+f"(C[nt][0]), "+f"(C[nt][1]), "+f"(C[nt][2]), "+f"(C[nt][3])
                    : "r"(a0), "r"(a1), "r"(a2), "r"(a3), "r"(bb.x), "r"(bb.y));
            }
            const uint2 bl = *(const uint2*)(cones + g * WSTh + par * 64 + ks * 16 + 4 * qt);
            asm volatile(
                "mma.sync.aligned.m16n8k16.row.col.f32.f16.f16.f32 "
                "{%0,%1,%2,%3}, {%4,%5,%6,%7}, {%8,%9}, {%0,%1,%2,%3};"
                : "+f"(C[4][0]), "+f"(C[4][1]), "+f"(C[4][2]), "+f"(C[4][3])
                : "r"(a0), "r"(a1), "r"(a2), "r"(a3), "r"(bl.x), "r"(bl.y));
        }

        __syncthreads();   // all warps done with buf[t&1]
        const int nc = t + 2;
        if (nc < NMT) {
            #pragma unroll
            for (int tt = 0; tt < 2; tt++) {
                const int idx = tid + tt * 256;
                const int row = idx >> 4, seg = idx & 15;
                uint32_t dp = (uint32_t)__cvta_generic_to_shared(&wh_sm[nc & 1][row * WSTh + seg * 8]);
                asm volatile("cp.async.ca.shared.global [%0], [%1], 16;"
                             :: "r"(dp), "l"(whg + (size_t)row * Nn + nc * TJm + seg * 8));
            }
        }
        asm volatile("cp.async.commit_group;" ::: "memory");   // unconditional
    }

    // l from the ones-column (tile 4, col 0): qt=0 lanes hold it; broadcast in quad.
    const float lA = __shfl_sync(FULLM, C[4][0], lane & ~3);
    const float lB = __shfl_sync(FULLM, C[4][2], lane & ~3);

    // ---- Combine the two j-halves (warps w and w+4 hold the same rows) ----
    float* Csc = (float*)mask_sm;          // masks dead after pass 2
    float* lsc = Csc + 64 * CST;
    if (par == 1) {
        #pragma unroll
        for (int nt = 0; nt < 4; nt++) {
            *(float2*)&Csc[lrA * CST + nt * 8 + 2 * qt] = make_float2(C[nt][0], C[nt][1]);
            *(float2*)&Csc[lrB * CST + nt * 8 + 2 * qt] = make_float2(C[nt][2], C[nt][3]);
        }
        if (qt == 0) { lsc[lrA] = lA; lsc[lrB] = lB; }
    }
    __syncthreads();
    if (par == 0) {
        #pragma unroll
        for (int nt = 0; nt < 4; nt++) {
            float2 cA = *(const float2*)&Csc[lrA * CST + nt * 8 + 2 * qt];
            float2 cB = *(const float2*)&Csc[lrB * CST + nt * 8 + 2 * qt];
            C[nt][0] += cA.x; C[nt][1] += cA.y;
            C[nt][2] += cB.x; C[nt][3] += cB.y;
        }
        const float tlA = lA + lsc[lrA];
        const float tlB = lB + lsc[lrB];
        const float rlA = (tlA > 0.f) ? (1.f / tlA) : 0.f;
        const float rlB = (tlB > 0.f) ? (1.f / tlB) : 0.f;
        const int iA = rbase + lrA;
        const int iB = rbase + lrB;
        float* outA = out + (size_t)(b * Nn + iA) * (Hn * Dn) + hd * Dn + 2 * qt;
        float* outB = out + (size_t)(b * Nn + iB) * (Hn * Dn) + hd * Dn + 2 * qt;
        #pragma unroll
        for (int nt = 0; nt < 4; nt++) {
            *(float2*)(outA + nt * 8) = make_float2(C[nt][0] * rlA, C[nt][1] * rlA);
            *(float2*)(outB + nt * 8) = make_float2(C[nt][2] * rlB, C[nt][3] * rlB);
        }
    }
}

extern "C" void kernel_launch(void* const* d_in, const int* in_sizes, int n_in,
                              void* d_out, int out_size)
{
    // Bind inputs by element count (robust to metadata ordering)
    const float* h = nullptr; const int* adj = nullptr;
    const float* W = nullptr; const float* a = nullptr;
    for (int i = 0; i < n_in; i++) {
        switch (in_sizes[i]) {
            case 1048576: h   = (const float*)d_in[i]; break;
            case 4194304: adj = (const int*)  d_in[i]; break;
            case 16384:   W   = (const float*)d_in[i]; break;
            case 256:     a   = (const float*)d_in[i]; break;
        }
    }
    float* out = (float*)d_out;

    proj_kernel<<<dim3(Bn, Nn / 16), 256>>>(h, W, a);
    attn_kernel<<<dim3(BH, Nn / 64), 256>>>(adj, out);
}

// round 14
// speedup vs baseline: 1.7890x; 1.0231x over previous
#include <cuda_runtime.h>
#include <cuda_fp16.h>
#include <cstdint>

// Problem dims (fixed): B=4, N=2048, F_in=128, H=4, D=32
#define Bn 4
#define Nn 2048
#define Fn 128
#define Hn 4
#define Dn 32
#define BH (Bn*Hn)
#define LOG2E 1.4426950408889634f
#define FULLM 0xffffffffu

__device__ __forceinline__ float ex2(float x) {
    float r; asm("ex2.approx.f32 %0, %1;" : "=f"(r) : "f"(x)); return r;
}

// Scratch (device globals; no allocation allowed).
// g_WhT layout: [bh][d][n'] fp16 where n' permutes n within each 16-group:
// positions [0,1,8,9,2,3,10,11,4,5,12,13,6,7,14,15] -> true n (B-fragment LDS.64).
__device__ __align__(256) __half g_WhT[BH * Dn * Nn];
__device__ __align__(16)  float g_es[BH * Nn];           // e_src (exact fp32)
__device__ __align__(16)  float g_ed[BH * Nn];           // e_dst (exact fp32)
__device__ __align__(256) __half g_W16T[Hn * Dn * Fn];   // W transposed [h][d][f] fp16
__device__ __align__(16)  float g_Was[Hn * Fn];          // W @ a_src  (exact fp32)
__device__ __align__(16)  float g_Wad[Hn * Fn];          // W @ a_dst  (exact fp32)

// -------------------- Kernel 0: fold a into W; transpose W to fp16 --------------------
// grid (Hn) x 128 threads: warp = f-chunk (32 f), lane = d.
__global__ __launch_bounds__(128) void prep_kernel(
    const float* __restrict__ W, const float* __restrict__ a)
{
    const int hh = blockIdx.x;
    const int wf = threadIdx.x >> 5;
    const int lane = threadIdx.x & 31;   // d
    const float a_s = __ldg(a + hh * (2 * Dn) + lane);
    const float a_d = __ldg(a + hh * (2 * Dn) + Dn + lane);
    for (int fi = 0; fi < 32; fi++) {
        const int f = wf * 32 + fi;
        const float w = __ldg(W + ((size_t)hh * Fn + f) * Dn + lane);
        g_W16T[(hh * Dn + lane) * Fn + f] = __float2half(w);
        float ps = w * a_s, pd = w * a_d;
        #pragma unroll
        for (int off = 16; off; off >>= 1) {
            ps += __shfl_xor_sync(FULLM, ps, off);
            pd += __shfl_xor_sync(FULLM, pd, off);
        }
        if (lane == 0) { g_Was[hh * Fn + f] = ps; g_Wad[hh * Fn + f] = pd; }
    }
}

// -------------------- Kernel A: es/ed (exact) + Wh via fp16 MMA --------------------
// grid (B, N/32) x 256 threads. Phase 1: load h fp32, exact es/ed, stage h fp16.
// Phase 2: warp = (head, d-half); WhT[16d x 32n] = W16T[16x128] @ h16[128x32].
#define PPAD 136   // h16 row stride (halfs)

__global__ __launch_bounds__(256) void proj_kernel(const float* __restrict__ h)
{
    __shared__ __align__(16) __half h16[32 * PPAD];   // 8.7 KB, [n][f]
    const int b  = blockIdx.x;
    const int n0 = blockIdx.y * 32;
    const int tid  = threadIdx.x;
    const int warp = tid >> 5;
    const int lane = tid & 31;

    // per-lane Wa registers: f = lane*4 .. +3 for each head
    float4 was[4], wad[4];
    #pragma unroll
    for (int hh = 0; hh < 4; hh++) {
        was[hh] = *(const float4*)(g_Was + hh * Fn + lane * 4);
        wad[hh] = *(const float4*)(g_Wad + hh * Fn + lane * 4);
    }

    // ---- Phase 1: warp handles rows 4*warp .. +3 ----
    #pragma unroll
    for (int r = 0; r < 4; r++) {
        const int n = warp * 4 + r;
        const float4 hv = *(const float4*)(h + ((size_t)(b * Nn + n0 + n)) * Fn + lane * 4);
        // stage fp16
        uint32_t p0, p1;
        asm("cvt.rn.f16x2.f32 %0, %1, %2;" : "=r"(p0) : "f"(hv.y), "f"(hv.x));
        asm("cvt.rn.f16x2.f32 %0, %1, %2;" : "=r"(p1) : "f"(hv.w), "f"(hv.z));
        *(uint2*)&h16[n * PPAD + lane * 4] = make_uint2(p0, p1);
        // exact fp32 es/ed partials
        float p[8];
        #pragma unroll
        for (int hh = 0; hh < 4; hh++) {
            p[hh]     = hv.x * was[hh].x + hv.y * was[hh].y + hv.z * was[hh].z + hv.w * was[hh].w;
            p[4 + hh] = hv.x * wad[hh].x + hv.y * wad[hh].y + hv.z * wad[hh].z + hv.w * wad[hh].w;
        }
        #pragma unroll
        for (int off = 16; off; off >>= 1)
            #pragma unroll
            for (int v = 0; v < 8; v++)
                p[v] += __shfl_xor_sync(FULLM, p[v], off);
        if (lane == 0) {
            #pragma unroll
            for (int hh = 0; hh < 4; hh++) {
                g_es[(b * Hn + hh) * Nn + n0 + n] = p[hh];
                g_ed[(b * Hn + hh) * Nn + n0 + n] = p[4 + hh];
            }
        }
    }
    __syncthreads();

    // ---- Phase 2: MMA. warp = (head = warp&3, dhalf = warp>>2) ----
    const int hh = warp & 3;
    const int dh = warp >> 2;
    const int g  = lane >> 2;
    const int qt = lane & 3;
    const __half* Wt = g_W16T + ((size_t)hh * Dn + dh * 16) * Fn;

    float C[4][4];
    #pragma unroll
    for (int nt = 0; nt < 4; nt++)
        #pragma unroll
        for (int k = 0; k < 4; k++) C[nt][k] = 0.f;

    #pragma unroll
    for (int ks = 0; ks < 8; ks++) {
        const int fk = ks * 16 + 2 * qt;
        const uint32_t a0 = *(const uint32_t*)(Wt + (size_t)g * Fn + fk);
        const uint32_t a1 = *(const uint32_t*)(Wt + (size_t)(g + 8) * Fn + fk);
        const uint32_t a2 = *(const uint32_t*)(Wt + (size_t)g * Fn + fk + 8);
        const uint32_t a3 = *(const uint32_t*)(Wt + (size_t)(g + 8) * Fn + fk + 8);
        #pragma unroll
        for (int nt = 0; nt < 4; nt++) {
            const uint32_t b0 = *(const uint32_t*)&h16[(nt * 8 + g) * PPAD + fk];
            const uint32_t b1 = *(const uint32_t*)&h16[(nt * 8 + g) * PPAD + fk + 8];
            asm volatile(
                "mma.sync.aligned.m16n8k16.row.col.f32.f16.f16.f32 "
                "{%0,%1,%2,%3}, {%4,%5,%6,%7}, {%8,%9}, {%0,%1,%2,%3};"
                : "+f"(C[nt][0]), "+f"(C[nt][1]), "+f"(C[nt][2]), "+f"(C[nt][3])
                : "r"(a0), "r"(a1), "r"(a2), "r"(a3), "r"(b0), "r"(b1));
        }
    }

    // ---- Epilogue: write WhT (permuted word layout, fp16) ----
    const int bh = b * Hn + hh;
    uint32_t* w0 = (uint32_t*)g_WhT + (((size_t)bh * Dn + dh * 16 + g) * Nn + n0) / 2;
    uint32_t* w8 = w0 + 8 * (Nn / 2);   // row g+8
    #pragma unroll
    for (int nt = 0; nt < 4; nt++) {
        const int widx = (nt >> 1) * 8 + 2 * qt + (nt & 1);
        uint32_t lo, hi;
        asm("cvt.rn.f16x2.f32 %0, %1, %2;" : "=r"(lo) : "f"(C[nt][1]), "f"(C[nt][0]));
        asm("cvt.rn.f16x2.f32 %0, %1, %2;" : "=r"(hi) : "f"(C[nt][3]), "f"(C[nt][2]));
        w0[widx] = lo;
        w8[widx] = hi;
    }
}

// -------------------- Kernel B: masked softmax + P@Wh via fp16 MMA --------------------
// (unchanged from the validated 73.3us kernel)
#define TJm 128
#define NMT (Nn / TJm)
#define WSTh 144
#define CST 34

__global__ __launch_bounds__(256, 3) void attn_kernel(
    const int* __restrict__ adj, float* __restrict__ out)
{
    __shared__ __align__(16) float    ed_sm[Nn];
    __shared__ __align__(16) unsigned mask_sm[64 * 64];
    __shared__ __align__(16) __half   wh_sm[2][32 * WSTh];
    __shared__ __align__(16) __half   cones[8 * WSTh];
    __shared__ float es1_sm[64], es2_sm[64];

    const int bh = blockIdx.x;
    const int b  = bh >> 2;
    const int hd = bh & 3;
    const int rbase = blockIdx.y * 64;
    const int tid  = threadIdx.x;
    const int warp = tid >> 5;
    const int lane = tid & 31;
    const int g  = lane >> 2;
    const int qt = lane & 3;
    const int par = warp >> 2;
    const int lrA = (warp & 3) * 16 + g;
    const int lrB = lrA + 8;

    const __half* whg = g_WhT + (size_t)bh * Dn * Nn;

    {
        const float4* src = (const float4*)(g_ed + bh * Nn);
        float4* dst = (float4*)ed_sm;
        #pragma unroll
        for (int r = 0; r < 2; r++) {
            float4 v = src[tid + r * 256];
            v.x *= LOG2E; v.y *= LOG2E; v.z *= LOG2E; v.w *= LOG2E;
            dst[tid + r * 256] = v;
        }
    }

    for (int i = tid; i < 8 * WSTh; i += 256)
        cones[i] = (i < WSTh) ? __float2half(1.f) : __float2half(0.f);

    #pragma unroll
    for (int c = 0; c < 2; c++) {
        #pragma unroll
        for (int tt = 0; tt < 2; tt++) {
            const int idx = tid + tt * 256;
            const int row = idx >> 4, seg = idx & 15;
            uint32_t dp = (uint32_t)__cvta_generic_to_shared(&wh_sm[c][row * WSTh + seg * 8]);
            asm volatile("cp.async.ca.shared.global [%0], [%1], 16;"
                         :: "r"(dp), "l"(whg + (size_t)row * Nn + c * TJm + seg * 8));
        }
        asm volatile("cp.async.commit_group;" ::: "memory");
    }

    __syncthreads();

    for (int k = 0; k < 8; k++) {
        const int lr = warp * 8 + k;
        const int r  = rbase + lr;
        const int* adjr = adj + (size_t)r * Nn;
        float m = -1e30f;
        #pragma unroll
        for (int it = 0; it < 16; it++) {
            uint4 av = __ldg((const uint4*)(adjr + it * 128 + lane * 4));
            float4 ev = *(const float4*)(ed_sm + it * 128 + lane * 4);
            unsigned m0 = __ballot_sync(FULLM, (int)av.x > 0);
            unsigned m1 = __ballot_sync(FULLM, (int)av.y > 0);
            unsigned m2 = __ballot_sync(FULLM, (int)av.z > 0);
            unsigned m3 = __ballot_sync(FULLM, (int)av.w > 0);
            if ((int)av.x > 0) m = fmaxf(m, ev.x);
            if ((int)av.y > 0) m = fmaxf(m, ev.y);
            if ((int)av.z > 0) m = fmaxf(m, ev.z);
            if ((int)av.w > 0) m = fmaxf(m, ev.w);
            if (lane == 0)
                *(uint4*)(mask_sm + lr * 64 + it * 4) = make_uint4(m0, m1, m2, m3);
        }
        #pragma unroll
        for (int off = 16; off; off >>= 1) m = fmaxf(m, __shfl_xor_sync(FULLM, m, off));
        if (lane == 0) {
            const float es = __ldg(g_es + bh * Nn + r) * LOG2E;
            float e1, e2;
            if (m < -9e29f) { e1 = -1e9f; e2 = -1e9f; }
            else {
                float s = es + m;
                float M = fmaxf(s, 0.2f * s);
                e1 = es - M;
                e2 = 0.2f * es - M;
            }
            es1_sm[lr] = e1; es2_sm[lr] = e2;
        }
    }
    __syncthreads();

    const float esA1 = es1_sm[lrA], esA2 = es2_sm[lrA];
    const float esB1 = es1_sm[lrB], esB2 = es2_sm[lrB];

    float C[5][4];
    #pragma unroll
    for (int nt = 0; nt < 5; nt++)
        #pragma unroll
        for (int k = 0; k < 4; k++) C[nt][k] = 0.f;

    const int c0 = 2 * (qt & 1);
    const int psh = par * 16 + (qt >> 1);

    for (int t = 0; t < NMT; t++) {
        asm volatile("cp.async.wait_group 1;" ::: "memory");
        __syncthreads();

        const uint2 mwA = *(const uint2*)&mask_sm[lrA * 64 + (t << 2) + c0];
        const uint2 mwB = *(const uint2*)&mask_sm[lrB * 64 + (t << 2) + c0];
        const unsigned wA0 = mwA.x >> psh;
        const unsigned wA1 = mwA.y >> psh;
        const unsigned wB0 = mwB.x >> psh;
        const unsigned wB1 = mwB.y >> psh;
        const int jb = t * TJm + par * 64;
        const __half* wbuf = wh_sm[t & 1] + par * 64;

        #pragma unroll
        for (int ks = 0; ks < 4; ks++) {
            const int j0 = jb + ks * 16 + 2 * qt;
            const float2 edlo = *(const float2*)(ed_sm + j0);
            const float2 edhi = *(const float2*)(ed_sm + j0 + 8);
            float t1, t2;
            float pA0 = 0.f, pA1 = 0.f, pA8 = 0.f, pA9 = 0.f;
            float pB0 = 0.f, pB1 = 0.f, pB8 = 0.f, pB9 = 0.f;
            t1 = esA1 + edlo.x; t2 = fmaf(0.2f, edlo.x, esA2);
            if (wA0 & (1u << (4 * ks)))     pA0 = ex2(fmaxf(t1, t2));
            t1 = esA1 + edlo.y; t2 = fmaf(0.2f, edlo.y, esA2);
            if (wA1 & (1u << (4 * ks)))     pA1 = ex2(fmaxf(t1, t2));
            t1 = esA1 + edhi.x; t2 = fmaf(0.2f, edhi.x, esA2);
            if (wA0 & (1u << (4 * ks + 2))) pA8 = ex2(fmaxf(t1, t2));
            t1 = esA1 + edhi.y; t2 = fmaf(0.2f, edhi.y, esA2);
            if (wA1 & (1u << (4 * ks + 2))) pA9 = ex2(fmaxf(t1, t2));
            t1 = esB1 + edlo.x; t2 = fmaf(0.2f, edlo.x, esB2);
            if (wB0 & (1u << (4 * ks)))     pB0 = ex2(fmaxf(t1, t2));
            t1 = esB1 + edlo.y; t2 = fmaf(0.2f, edlo.y, esB2);
            if (wB1 & (1u << (4 * ks)))     pB1 = ex2(fmaxf(t1, t2));
            t1 = esB1 + edhi.x; t2 = fmaf(0.2f, edhi.x, esB2);
            if (wB0 & (1u << (4 * ks + 2))) pB8 = ex2(fmaxf(t1, t2));
            t1 = esB1 + edhi.y; t2 = fmaf(0.2f, edhi.y, esB2);
            if (wB1 & (1u << (4 * ks + 2))) pB9 = ex2(fmaxf(t1, t2));
            uint32_t a0, a1, a2, a3;
            asm("cvt.rn.f16x2.f32 %0, %1, %2;" : "=r"(a0) : "f"(pA1), "f"(pA0));
            asm("cvt.rn.f16x2.f32 %0, %1, %2;" : "=r"(a1) : "f"(pB1), "f"(pB0));
            asm("cvt.rn.f16x2.f32 %0, %1, %2;" : "=r"(a2) : "f"(pA9), "f"(pA8));
            asm("cvt.rn.f16x2.f32 %0, %1, %2;" : "=r"(a3) : "f"(pB9), "f"(pB8));
            const __half* bpt = wbuf + ks * 16 + 4 * qt;
            #pragma unroll
            for (int nt = 0; nt < 4; nt++) {
                const uint2 bb = *(const uint2*)(bpt + (nt * 8 + g) * WSTh);
                asm volatile(
                    "mma.sync.aligned.m16n8k16.row.col.f32.f16.f16.f32 "
                    "{%0,%1,%2,%3}, {%4,%5,%6,%7}, {%8,%9}, {%0,%1,%2,%3};"
                    : "+f"(C[nt][0]), "+f"(C[nt][1]), "+f"(C[nt][2]), "+f"(C[nt][3])
                    : "r"(a0), "r"(a1), "r"(a2), "r"(a3), "r"(bb.x), "r"(bb.y));
            }
            const uint2 bl = *(const uint2*)(cones + g * WSTh + par * 64 + ks * 16 + 4 * qt);
            asm volatile(
                "mma.sync.aligned.m16n8k16.row.col.f32.f16.f16.f32 "
                "{%0,%1,%2,%3}, {%4,%5,%6,%7}, {%8,%9}, {%0,%1,%2,%3};"
                : "+f"(C[4][0]), "+f"(C[4][1]), "+f"(C[4][2]), "+f"(C[4][3])
                : "r"(a0), "r"(a1), "r"(a2), "r"(a3), "r"(bl.x), "r"(bl.y));
        }

        __syncthreads();
        const int nc = t + 2;
        if (nc < NMT) {
            #pragma unroll
            for (int tt = 0; tt < 2; tt++) {
                const int idx = tid + tt * 256;
                const int row = idx >> 4, seg = idx & 15;
                uint32_t dp = (uint32_t)__cvta_generic_to_shared(&wh_sm[nc & 1][row * WSTh + seg * 8]);
                asm volatile("cp.async.ca.shared.global [%0], [%1], 16;"
                             :: "r"(dp), "l"(whg + (size_t)row * Nn + nc * TJm + seg * 8));
            }
        }
        asm volatile("cp.async.commit_group;" ::: "memory");
    }

    const float lA = __shfl_sync(FULLM, C[4][0], lane & ~3);
    const float lB = __shfl_sync(FULLM, C[4][2], lane & ~3);

    float* Csc = (float*)mask_sm;
    float* lsc = Csc + 64 * CST;
    if (par == 1) {
        #pragma unroll
        for (int nt = 0; nt < 4; nt++) {
            *(float2*)&Csc[lrA * CST + nt * 8 + 2 * qt] = make_float2(C[nt][0], C[nt][1]);
            *(float2*)&Csc[lrB * CST + nt * 8 + 2 * qt] = make_float2(C[nt][2], C[nt][3]);
        }
        if (qt == 0) { lsc[lrA] = lA; lsc[lrB] = lB; }
    }
    __syncthreads();
    if (par == 0) {
        #pragma unroll
        for (int nt = 0; nt < 4; nt++) {
            float2 cA = *(const float2*)&Csc[lrA * CST + nt * 8 + 2 * qt];
            float2 cB = *(const float2*)&Csc[lrB * CST + nt * 8 + 2 * qt];
            C[nt][0] += cA.x; C[nt][1] += cA.y;
            C[nt][2] += cB.x; C[nt][3] += cB.y;
        }
        const float tlA = lA + lsc[lrA];
        const float tlB = lB + lsc[lrB];
        const float rlA = (tlA > 0.f) ? (1.f / tlA) : 0.f;
        const float rlB = (tlB > 0.f) ? (1.f / tlB) : 0.f;
        const int iA = rbase + lrA;
        const int iB = rbase + lrB;
        float* outA = out + (size_t)(b * Nn + iA) * (Hn * Dn) + hd * Dn + 2 * qt;
        float* outB = out + (size_t)(b * Nn + iB) * (Hn * Dn) + hd * Dn + 2 * qt;
        #pragma unroll
        for (int nt = 0; nt < 4; nt++) {
            *(float2*)(outA + nt * 8) = make_float2(C[nt][0] * rlA, C[nt][1] * rlA);
            *(float2*)(outB + nt * 8) = make_float2(C[nt][2] * rlB, C[nt][3] * rlB);
        }
    }
}

extern "C" void kernel_launch(void* const* d_in, const int* in_sizes, int n_in,
                              void* d_out, int out_size)
{
    // Bind inputs by element count (robust to metadata ordering)
    const float* h = nullptr; const int* adj = nullptr;
    const float* W = nullptr; const float* a = nullptr;
    for (int i = 0; i < n_in; i++) {
        switch (in_sizes[i]) {
            case 1048576: h   = (const float*)d_in[i]; break;
            case 4194304: adj = (const int*)  d_in[i]; break;
            case 16384:   W   = (const float*)d_in[i]; break;
            case 256:     a   = (const float*)d_in[i]; break;
        }
    }
    float* out = (float*)d_out;

    prep_kernel<<<Hn, 128>>>(W, a);
    proj_kernel<<<dim3(Bn, Nn / 32), 256>>>(h);
    attn_kernel<<<dim3(BH, Nn / 64), 256>>>(adj, out);
}

// round 15
// speedup vs baseline: 1.8850x; 1.0537x over previous
#include <cuda_runtime.h>
#include <cuda_fp16.h>
#include <cstdint>

// Problem dims (fixed): B=4, N=2048, F_in=128, H=4, D=32
#define Bn 4
#define Nn 2048
#define Fn 128
#define Hn 4
#define Dn 32
#define BH (Bn*Hn)
#define LOG2E 1.4426950408889634f
#define FULLM 0xffffffffu

__device__ __forceinline__ float ex2(float x) {
    float r; asm("ex2.approx.f32 %0, %1;" : "=f"(r) : "f"(x)); return r;
}

// Scratch (device globals; no allocation allowed).
// g_WhT layout: [bh][d][n'] fp16 where n' permutes n within each 16-group:
// positions [0,1,8,9,2,3,10,11,4,5,12,13,6,7,14,15] -> true n (B-fragment LDS.64).
__device__ __align__(256) __half g_WhT[BH * Dn * Nn];
__device__ __align__(16)  float g_es[BH * Nn];           // e_src (exact fp32)
__device__ __align__(16)  float g_ed[BH * Nn];           // e_dst (exact fp32)
__device__ __align__(256) __half g_W16T[Hn * Dn * Fn];   // W transposed [h][d][f] fp16
__device__ __align__(16)  float g_Was[Hn * Fn];          // W @ a_src  (exact fp32)
__device__ __align__(16)  float g_Wad[Hn * Fn];          // W @ a_dst  (exact fp32)

// -------------------- Kernel 0: fold a into W; transpose W to fp16 --------------------
// 512 (h,f) rows; grid 16 x 256 threads = 128 warps, 4 rows/warp, lane = d.
__global__ __launch_bounds__(256) void prep_kernel(
    const float* __restrict__ W, const float* __restrict__ a)
{
    const int warp = threadIdx.x >> 5;
    const int lane = threadIdx.x & 31;   // d
    const int wid  = blockIdx.x * 8 + warp;   // 0..127
    const int row0 = wid * 4;                 // rows row0..row0+3 share a head
    const int hh   = row0 >> 7;
    const float a_s = __ldg(a + hh * (2 * Dn) + lane);
    const float a_d = __ldg(a + hh * (2 * Dn) + Dn + lane);
    #pragma unroll
    for (int r = 0; r < 4; r++) {
        const int row = row0 + r;        // = hh*128 + f
        const int f   = row & 127;
        const float w = __ldg(W + (size_t)row * Dn + lane);
        g_W16T[(hh * Dn + lane) * Fn + f] = __float2half(w);
        float ps = w * a_s, pd = w * a_d;
        #pragma unroll
        for (int off = 16; off; off >>= 1) {
            ps += __shfl_xor_sync(FULLM, ps, off);
            pd += __shfl_xor_sync(FULLM, pd, off);
        }
        if (lane == 0) { g_Was[hh * Fn + f] = ps; g_Wad[hh * Fn + f] = pd; }
    }
}

// -------------------- Kernel A: es/ed (exact) + Wh via fp16 MMA --------------------
// grid (B, N/32) x 256 threads. Phase 1: load h fp32, exact es/ed, stage h fp16.
// Phase 2: warp = (head, d-half); WhT[16d x 32n] = W16T[16x128] @ h16[128x32].
#define PPAD 136   // h16 row stride (halfs)

__global__ __launch_bounds__(256) void proj_kernel(const float* __restrict__ h)
{
    __shared__ __align__(16) __half h16[32 * PPAD];   // 8.7 KB, [n][f]
    const int b  = blockIdx.x;
    const int n0 = blockIdx.y * 32;
    const int tid  = threadIdx.x;
    const int warp = tid >> 5;
    const int lane = tid & 31;

    // per-lane Wa registers: f = lane*4 .. +3 for each head
    float4 was[4], wad[4];
    #pragma unroll
    for (int hh = 0; hh < 4; hh++) {
        was[hh] = *(const float4*)(g_Was + hh * Fn + lane * 4);
        wad[hh] = *(const float4*)(g_Wad + hh * Fn + lane * 4);
    }

    // ---- Phase 1: warp handles rows 4*warp .. +3 ----
    #pragma unroll
    for (int r = 0; r < 4; r++) {
        const int n = warp * 4 + r;
        const float4 hv = *(const float4*)(h + ((size_t)(b * Nn + n0 + n)) * Fn + lane * 4);
        // stage fp16
        uint32_t p0, p1;
        asm("cvt.rn.f16x2.f32 %0, %1, %2;" : "=r"(p0) : "f"(hv.y), "f"(hv.x));
        asm("cvt.rn.f16x2.f32 %0, %1, %2;" : "=r"(p1) : "f"(hv.w), "f"(hv.z));
        *(uint2*)&h16[n * PPAD + lane * 4] = make_uint2(p0, p1);
        // exact fp32 es/ed partials
        float p[8];
        #pragma unroll
        for (int hh = 0; hh < 4; hh++) {
            p[hh]     = hv.x * was[hh].x + hv.y * was[hh].y + hv.z * was[hh].z + hv.w * was[hh].w;
            p[4 + hh] = hv.x * wad[hh].x + hv.y * wad[hh].y + hv.z * wad[hh].z + hv.w * wad[hh].w;
        }
        #pragma unroll
        for (int off = 16; off; off >>= 1)
            #pragma unroll
            for (int v = 0; v < 8; v++)
                p[v] += __shfl_xor_sync(FULLM, p[v], off);
        if (lane == 0) {
            #pragma unroll
            for (int hh = 0; hh < 4; hh++) {
                g_es[(b * Hn + hh) * Nn + n0 + n] = p[hh];
                g_ed[(b * Hn + hh) * Nn + n0 + n] = p[4 + hh];
            }
        }
    }
    __syncthreads();

    // ---- Phase 2: MMA. warp = (head = warp&3, dhalf = warp>>2) ----
    const int hh = warp & 3;
    const int dh = warp >> 2;
    const int g  = lane >> 2;
    const int qt = lane & 3;
    const __half* Wt = g_W16T + ((size_t)hh * Dn + dh * 16) * Fn;

    float C[4][4];
    #pragma unroll
    for (int nt = 0; nt < 4; nt++)
        #pragma unroll
        for (int k = 0; k < 4; k++) C[nt][k] = 0.f;

    #pragma unroll
    for (int ks = 0; ks < 8; ks++) {
        const int fk = ks * 16 + 2 * qt;
        const uint32_t a0 = *(const uint32_t*)(Wt + (size_t)g * Fn + fk);
        const uint32_t a1 = *(const uint32_t*)(Wt + (size_t)(g + 8) * Fn + fk);
        const uint32_t a2 = *(const uint32_t*)(Wt + (size_t)g * Fn + fk + 8);
        const uint32_t a3 = *(const uint32_t*)(Wt + (size_t)(g + 8) * Fn + fk + 8);
        #pragma unroll
        for (int nt = 0; nt < 4; nt++) {
            const uint32_t b0 = *(const uint32_t*)&h16[(nt * 8 + g) * PPAD + fk];
            const uint32_t b1 = *(const uint32_t*)&h16[(nt * 8 + g) * PPAD + fk + 8];
            asm volatile(
                "mma.sync.aligned.m16n8k16.row.col.f32.f16.f16.f32 "
                "{%0,%1,%2,%3}, {%4,%5,%6,%7}, {%8,%9}, {%0,%1,%2,%3};"
                : "+f"(C[nt][0]), "+f"(C[nt][1]), "+f"(C[nt][2]), "+f"(C[nt][3])
                : "r"(a0), "r"(a1), "r"(a2), "r"(a3), "r"(b0), "r"(b1));
        }
    }

    // ---- Epilogue: write WhT (permuted word layout, fp16) ----
    const int bh = b * Hn + hh;
    uint32_t* w0 = (uint32_t*)g_WhT + (((size_t)bh * Dn + dh * 16 + g) * Nn + n0) / 2;
    uint32_t* w8 = w0 + 8 * (Nn / 2);   // row g+8
    #pragma unroll
    for (int nt = 0; nt < 4; nt++) {
        const int widx = (nt >> 1) * 8 + 2 * qt + (nt & 1);
        uint32_t lo, hi;
        asm("cvt.rn.f16x2.f32 %0, %1, %2;" : "=r"(lo) : "f"(C[nt][1]), "f"(C[nt][0]));
        asm("cvt.rn.f16x2.f32 %0, %1, %2;" : "=r"(hi) : "f"(C[nt][3]), "f"(C[nt][2]));
        w0[widx] = lo;
        w8[widx] = hi;
    }
}

// -------------------- Kernel B: masked softmax + P@Wh via fp16 MMA --------------------
// (unchanged from the validated 73.3us kernel)
#define TJm 128
#define NMT (Nn / TJm)
#define WSTh 144
#define CST 34

__global__ __launch_bounds__(256, 3) void attn_kernel(
    const int* __restrict__ adj, float* __restrict__ out)
{
    __shared__ __align__(16) float    ed_sm[Nn];
    __shared__ __align__(16) unsigned mask_sm[64 * 64];
    __shared__ __align__(16) __half   wh_sm[2][32 * WSTh];
    __shared__ __align__(16) __half   cones[8 * WSTh];
    __shared__ float es1_sm[64], es2_sm[64];

    const int bh = blockIdx.x;
    const int b  = bh >> 2;
    const int hd = bh & 3;
    const int rbase = blockIdx.y * 64;
    const int tid  = threadIdx.x;
    const int warp = tid >> 5;
    const int lane = tid & 31;
    const int g  = lane >> 2;
    const int qt = lane & 3;
    const int par = warp >> 2;
    const int lrA = (warp & 3) * 16 + g;
    const int lrB = lrA + 8;

    const __half* whg = g_WhT + (size_t)bh * Dn * Nn;

    {
        const float4* src = (const float4*)(g_ed + bh * Nn);
        float4* dst = (float4*)ed_sm;
        #pragma unroll
        for (int r = 0; r < 2; r++) {
            float4 v = src[tid + r * 256];
            v.x *= LOG2E; v.y *= LOG2E; v.z *= LOG2E; v.w *= LOG2E;
            dst[tid + r * 256] = v;
        }
    }

    for (int i = tid; i < 8 * WSTh; i += 256)
        cones[i] = (i < WSTh) ? __float2half(1.f) : __float2half(0.f);

    #pragma unroll
    for (int c = 0; c < 2; c++) {
        #pragma unroll
        for (int tt = 0; tt < 2; tt++) {
            const int idx = tid + tt * 256;
            const int row = idx >> 4, seg = idx & 15;
            uint32_t dp = (uint32_t)__cvta_generic_to_shared(&wh_sm[c][row * WSTh + seg * 8]);
            asm volatile("cp.async.ca.shared.global [%0], [%1], 16;"
                         :: "r"(dp), "l"(whg + (size_t)row * Nn + c * TJm + seg * 8));
        }
        asm volatile("cp.async.commit_group;" ::: "memory");
    }

    __syncthreads();

    for (int k = 0; k < 8; k++) {
        const int lr = warp * 8 + k;
        const int r  = rbase + lr;
        const int* adjr = adj + (size_t)r * Nn;
        float m = -1e30f;
        #pragma unroll
        for (int it = 0; it < 16; it++) {
            uint4 av = __ldg((const uint4*)(adjr + it * 128 + lane * 4));
            float4 ev = *(const float4*)(ed_sm + it * 128 + lane * 4);
            unsigned m0 = __ballot_sync(FULLM, (int)av.x > 0);
            unsigned m1 = __ballot_sync(FULLM, (int)av.y > 0);
            unsigned m2 = __ballot_sync(FULLM, (int)av.z > 0);
            unsigned m3 = __ballot_sync(FULLM, (int)av.w > 0);
            if ((int)av.x > 0) m = fmaxf(m, ev.x);
            if ((int)av.y > 0) m = fmaxf(m, ev.y);
            if ((int)av.z > 0) m = fmaxf(m, ev.z);
            if ((int)av.w > 0) m = fmaxf(m, ev.w);
            if (lane == 0)
                *(uint4*)(mask_sm + lr * 64 + it * 4) = make_uint4(m0, m1, m2, m3);
        }
        #pragma unroll
        for (int off = 16; off; off >>= 1) m = fmaxf(m, __shfl_xor_sync(FULLM, m, off));
        if (lane == 0) {
            const float es = __ldg(g_es + bh * Nn + r) * LOG2E;
            float e1, e2;
            if (m < -9e29f) { e1 = -1e9f; e2 = -1e9f; }
            else {
                float s = es + m;
                float M = fmaxf(s, 0.2f * s);
                e1 = es - M;
                e2 = 0.2f * es - M;
            }
            es1_sm[lr] = e1; es2_sm[lr] = e2;
        }
    }
    __syncthreads();

    const float esA1 = es1_sm[lrA], esA2 = es2_sm[lrA];
    const float esB1 = es1_sm[lrB], esB2 = es2_sm[lrB];

    float C[5][4];
    #pragma unroll
    for (int nt = 0; nt < 5; nt++)
        #pragma unroll
        for (int k = 0; k < 4; k++) C[nt][k] = 0.f;

    const int c0 = 2 * (qt & 1);
    const int psh = par * 16 + (qt >> 1);

    for (int t = 0; t < NMT; t++) {
        asm volatile("cp.async.wait_group 1;" ::: "memory");
        __syncthreads();

        const uint2 mwA = *(const uint2*)&mask_sm[lrA * 64 + (t << 2) + c0];
        const uint2 mwB = *(const uint2*)&mask_sm[lrB * 64 + (t << 2) + c0];
        const unsigned wA0 = mwA.x >> psh;
        const unsigned wA1 = mwA.y >> psh;
        const unsigned wB0 = mwB.x >> psh;
        const unsigned wB1 = mwB.y >> psh;
        const int jb = t * TJm + par * 64;
        const __half* wbuf = wh_sm[t & 1] + par * 64;

        #pragma unroll
        for (int ks = 0; ks < 4; ks++) {
            const int j0 = jb + ks * 16 + 2 * qt;
            const float2 edlo = *(const float2*)(ed_sm + j0);
            const float2 edhi = *(const float2*)(ed_sm + j0 + 8);
            float t1, t2;
            float pA0 = 0.f, pA1 = 0.f, pA8 = 0.f, pA9 = 0.f;
            float pB0 = 0.f, pB1 = 0.f, pB8 = 0.f, pB9 = 0.f;
            t1 = esA1 + edlo.x; t2 = fmaf(0.2f, edlo.x, esA2);
            if (wA0 & (1u << (4 * ks)))     pA0 = ex2(fmaxf(t1, t2));
            t1 = esA1 + edlo.y; t2 = fmaf(0.2f, edlo.y, esA2);
            if (wA1 & (1u << (4 * ks)))     pA1 = ex2(fmaxf(t1, t2));
            t1 = esA1 + edhi.x; t2 = fmaf(0.2f, edhi.x, esA2);
            if (wA0 & (1u << (4 * ks + 2))) pA8 = ex2(fmaxf(t1, t2));
            t1 = esA1 + edhi.y; t2 = fmaf(0.2f, edhi.y, esA2);
            if (wA1 & (1u << (4 * ks + 2))) pA9 = ex2(fmaxf(t1, t2));
            t1 = esB1 + edlo.x; t2 = fmaf(0.2f, edlo.x, esB2);
            if (wB0 & (1u << (4 * ks)))     pB0 = ex2(fmaxf(t1, t2));
            t1 = esB1 + edlo.y; t2 = fmaf(0.2f, edlo.y, esB2);
            if (wB1 & (1u << (4 * ks)))     pB1 = ex2(fmaxf(t1, t2));
            t1 = esB1 + edhi.x; t2 = fmaf(0.2f, edhi.x, esB2);
            if (wB0 & (1u << (4 * ks + 2))) pB8 = ex2(fmaxf(t1, t2));
            t1 = esB1 + edhi.y; t2 = fmaf(0.2f, edhi.y, esB2);
            if (wB1 & (1u << (4 * ks + 2))) pB9 = ex2(fmaxf(t1, t2));
            uint32_t a0, a1, a2, a3;
            asm("cvt.rn.f16x2.f32 %0, %1, %2;" : "=r"(a0) : "f"(pA1), "f"(pA0));
            asm("cvt.rn.f16x2.f32 %0, %1, %2;" : "=r"(a1) : "f"(pB1), "f"(pB0));
            asm("cvt.rn.f16x2.f32 %0, %1, %2;" : "=r"(a2) : "f"(pA9), "f"(pA8));
            asm("cvt.rn.f16x2.f32 %0, %1, %2;" : "=r"(a3) : "f"(pB9), "f"(pB8));
            const __half* bpt = wbuf + ks * 16 + 4 * qt;
            #pragma unroll
            for (int nt = 0; nt < 4; nt++) {
                const uint2 bb = *(const uint2*)(bpt + (nt * 8 + g) * WSTh);
                asm volatile(
                    "mma.sync.aligned.m16n8k16.row.col.f32.f16.f16.f32 "
                    "{%0,%1,%2,%3}, {%4,%5,%6,%7}, {%8,%9}, {%0,%1,%2,%3};"
                    : "+f"(C[nt][0]), "+f"(C[nt][1]), "+f"(C[nt][2]), "+f"(C[nt][3])
                    : "r"(a0), "r"(a1), "r"(a2), "r"(a3), "r"(bb.x), "r"(bb.y));
            }
            const uint2 bl = *(const uint2*)(cones + g * WSTh + par * 64 + ks * 16 + 4 * qt);
            asm volatile(
                "mma.sync.aligned.m16n8k16.row.col.f32.f16.f16.f32 "
                "{%0,%1,%2,%3}, {%4,%5,%6,%7}, {%8,%9}, {%0,%1,%2,%3};"
                : "+f"(C[4][0]), "+f"(C[4][1]), "+f"(C[4][2]), "+f"(C[4][3])
                : "r"(a0), "r"(a1), "r"(a2), "r"(a3), "r"(bl.x), "r"(bl.y));
        }

        __syncthreads();
        const int nc = t + 2;
        if (nc < NMT) {
            #pragma unroll
            for (int tt = 0; tt < 2; tt++) {
                const int idx = tid + tt * 256;
                const int row = idx >> 4, seg = idx & 15;
                uint32_t dp = (uint32_t)__cvta_generic_to_shared(&wh_sm[nc & 1][row * WSTh + seg * 8]);
                asm volatile("cp.async.ca.shared.global [%0], [%1], 16;"
                             :: "r"(dp), "l"(whg + (size_t)row * Nn + nc * TJm + seg * 8));
            }
        }
        asm volatile("cp.async.commit_group;" ::: "memory");
    }

    const float lA = __shfl_sync(FULLM, C[4][0], lane & ~3);
    const float lB = __shfl_sync(FULLM, C[4][2], lane & ~3);

    float* Csc = (float*)mask_sm;
    float* lsc = Csc + 64 * CST;
    if (par == 1) {
        #pragma unroll
        for (int nt = 0; nt < 4; nt++) {
            *(float2*)&Csc[lrA * CST + nt * 8 + 2 * qt] = make_float2(C[nt][0], C[nt][1]);
            *(float2*)&Csc[lrB * CST + nt * 8 + 2 * qt] = make_float2(C[nt][2], C[nt][3]);
        }
        if (qt == 0) { lsc[lrA] = lA; lsc[lrB] = lB; }
    }
    __syncthreads();
    if (par == 0) {
        #pragma unroll
        for (int nt = 0; nt < 4; nt++) {
            float2 cA = *(const float2*)&Csc[lrA * CST + nt * 8 + 2 * qt];
            float2 cB = *(const float2*)&Csc[lrB * CST + nt * 8 + 2 * qt];
            C[nt][0] += cA.x; C[nt][1] += cA.y;
            C[nt][2] += cB.x; C[nt][3] += cB.y;
        }
        const float tlA = lA + lsc[lrA];
        const float tlB = lB + lsc[lrB];
        const float rlA = (tlA > 0.f) ? (1.f / tlA) : 0.f;
        const float rlB = (tlB > 0.f) ? (1.f / tlB) : 0.f;
        const int iA = rbase + lrA;
        const int iB = rbase + lrB;
        float* outA = out + (size_t)(b * Nn + iA) * (Hn * Dn) + hd * Dn + 2 * qt;
        float* outB = out + (size_t)(b * Nn + iB) * (Hn * Dn) + hd * Dn + 2 * qt;
        #pragma unroll
        for (int nt = 0; nt < 4; nt++) {
            *(float2*)(outA + nt * 8) = make_float2(C[nt][0] * rlA, C[nt][1] * rlA);
            *(float2*)(outB + nt * 8) = make_float2(C[nt][2] * rlB, C[nt][3] * rlB);
        }
    }
}

extern "C" void kernel_launch(void* const* d_in, const int* in_sizes, int n_in,
                              void* d_out, int out_size)
{
    // Bind inputs by element count (robust to metadata ordering)
    const float* h = nullptr; const int* adj = nullptr;
    const float* W = nullptr; const float* a = nullptr;
    for (int i = 0; i < n_in; i++) {
        switch (in_sizes[i]) {
            case 1048576: h   = (const float*)d_in[i]; break;
            case 4194304: adj = (const int*)  d_in[i]; break;
            case 16384:   W   = (const float*)d_in[i]; break;
            case 256:     a   = (const float*)d_in[i]; break;
        }
    }
    float* out = (float*)d_out;

    prep_kernel<<<16, 256>>>(W, a);
    proj_kernel<<<dim3(Bn, Nn / 32), 256>>>(h);
    attn_kernel<<<dim3(BH, Nn / 64), 256>>>(adj, out);
}

// round 16
// speedup vs baseline: 2.0711x; 1.0987x over previous
#include <cuda_runtime.h>
#include <cuda_fp16.h>
#include <cstdint>

// Problem dims (fixed): B=4, N=2048, F_in=128, H=4, D=32
#define Bn 4
#define Nn 2048
#define Fn 128
#define Hn 4
#define Dn 32
#define BH (Bn*Hn)
#define LOG2E 1.4426950408889634f
#define FULLM 0xffffffffu
typedef unsigned long long ull;

__device__ __forceinline__ float ex2(float x) {
    float r; asm("ex2.approx.f32 %0, %1;" : "=f"(r) : "f"(x)); return r;
}
__device__ __forceinline__ ull pack2(float x) {
    ull r; asm("mov.b64 %0, {%1, %1};" : "=l"(r) : "f"(x)); return r;
}
// packed f32x2 score: a0/a1 = max(es1 + e, 0.2*e + es2) for the two packed e's
__device__ __forceinline__ void score2(ull ed2, ull es1x2, ull es2x2, ull c02,
                                       float& a0, float& a1)
{
    ull t1, t2;
    asm("add.rn.f32x2 %0, %1, %2;" : "=l"(t1) : "l"(es1x2), "l"(ed2));
    asm("fma.rn.f32x2 %0, %1, %2, %3;" : "=l"(t2) : "l"(c02), "l"(ed2), "l"(es2x2));
    float t1l, t1h, t2l, t2h;
    asm("mov.b64 {%0,%1}, %2;" : "=f"(t1l), "=f"(t1h) : "l"(t1));
    asm("mov.b64 {%0,%1}, %2;" : "=f"(t2l), "=f"(t2h) : "l"(t2));
    a0 = fmaxf(t1l, t2l);
    a1 = fmaxf(t1h, t2h);
}

// Scratch (device globals; no allocation allowed).
// g_WhT layout: [bh][d][n'] fp16, n' permutes n within each 16-group (B-frag LDS.64).
__device__ __align__(256) __half g_WhT[BH * Dn * Nn];
__device__ __align__(16)  float g_es[BH * Nn];           // e_src (exact fp32)
__device__ __align__(16)  float g_ed[BH * Nn];           // e_dst (exact fp32)
__device__ __align__(256) __half g_W16T[Hn * Dn * Fn];   // W transposed [h][d][f] fp16
__device__ __align__(16)  float g_Was[Hn * Fn];          // W @ a_src  (exact fp32)
__device__ __align__(16)  float g_Wad[Hn * Fn];          // W @ a_dst  (exact fp32)
__device__ __align__(256) unsigned g_mask[Nn * 64];      // adjacency bitmasks (shared by all bh)

// -------------------- Kernel 0 (fused): prep (blocks 0-15) + mask pack (16-79) -------
__global__ __launch_bounds__(256) void setup_kernel(
    const float* __restrict__ W, const float* __restrict__ a,
    const int* __restrict__ adj)
{
    const int warp = threadIdx.x >> 5;
    const int lane = threadIdx.x & 31;

    if (blockIdx.x < 16) {
        // prep: fold a into W, transpose W to fp16. 512 (h,f) rows, 4 per warp.
        const int wid  = blockIdx.x * 8 + warp;
        const int row0 = wid * 4;
        const int hh   = row0 >> 7;
        const float a_s = __ldg(a + hh * (2 * Dn) + lane);
        const float a_d = __ldg(a + hh * (2 * Dn) + Dn + lane);
        #pragma unroll
        for (int r = 0; r < 4; r++) {
            const int row = row0 + r;
            const int f   = row & 127;
            const float w = __ldg(W + (size_t)row * Dn + lane);
            g_W16T[(hh * Dn + lane) * Fn + f] = __float2half(w);
            float ps = w * a_s, pd = w * a_d;
            #pragma unroll
            for (int off = 16; off; off >>= 1) {
                ps += __shfl_xor_sync(FULLM, ps, off);
                pd += __shfl_xor_sync(FULLM, pd, off);
            }
            if (lane == 0) { g_Was[hh * Fn + f] = ps; g_Wad[hh * Fn + f] = pd; }
        }
    } else {
        // mask pack: 2048 adj rows -> bitmasks, once for all 16 bh.
        // word (row, it*4+c) bit L <-> adj[row][it*128 + 4L + c]
        const int mb = blockIdx.x - 16;          // 0..63
        #pragma unroll
        for (int r = 0; r < 4; r++) {
            const int row = mb * 32 + warp * 4 + r;
            const int* adjr = adj + (size_t)row * Nn;
            #pragma unroll
            for (int it = 0; it < 16; it++) {
                uint4 av = __ldg((const uint4*)(adjr + it * 128 + lane * 4));
                unsigned m0 = __ballot_sync(FULLM, (int)av.x > 0);
                unsigned m1 = __ballot_sync(FULLM, (int)av.y > 0);
                unsigned m2 = __ballot_sync(FULLM, (int)av.z > 0);
                unsigned m3 = __ballot_sync(FULLM, (int)av.w > 0);
                if (lane == 0)
                    *(uint4*)&g_mask[row * 64 + it * 4] = make_uint4(m0, m1, m2, m3);
            }
        }
    }
}

// -------------------- Kernel A: es/ed (exact) + Wh via fp16 MMA --------------------
#define PPAD 136   // h16 row stride (halfs)

__global__ __launch_bounds__(256) void proj_kernel(const float* __restrict__ h)
{
    __shared__ __align__(16) __half h16[32 * PPAD];
    const int b  = blockIdx.x;
    const int n0 = blockIdx.y * 32;
    const int tid  = threadIdx.x;
    const int warp = tid >> 5;
    const int lane = tid & 31;

    float4 was[4], wad[4];
    #pragma unroll
    for (int hh = 0; hh < 4; hh++) {
        was[hh] = *(const float4*)(g_Was + hh * Fn + lane * 4);
        wad[hh] = *(const float4*)(g_Wad + hh * Fn + lane * 4);
    }

    #pragma unroll
    for (int r = 0; r < 4; r++) {
        const int n = warp * 4 + r;
        const float4 hv = *(const float4*)(h + ((size_t)(b * Nn + n0 + n)) * Fn + lane * 4);
        uint32_t p0, p1;
        asm("cvt.rn.f16x2.f32 %0, %1, %2;" : "=r"(p0) : "f"(hv.y), "f"(hv.x));
        asm("cvt.rn.f16x2.f32 %0, %1, %2;" : "=r"(p1) : "f"(hv.w), "f"(hv.z));
        *(uint2*)&h16[n * PPAD + lane * 4] = make_uint2(p0, p1);
        float p[8];
        #pragma unroll
        for (int hh = 0; hh < 4; hh++) {
            p[hh]     = hv.x * was[hh].x + hv.y * was[hh].y + hv.z * was[hh].z + hv.w * was[hh].w;
            p[4 + hh] = hv.x * wad[hh].x + hv.y * wad[hh].y + hv.z * wad[hh].z + hv.w * wad[hh].w;
        }
        #pragma unroll
        for (int off = 16; off; off >>= 1)
            #pragma unroll
            for (int v = 0; v < 8; v++)
                p[v] += __shfl_xor_sync(FULLM, p[v], off);
        if (lane == 0) {
            #pragma unroll
            for (int hh = 0; hh < 4; hh++) {
                g_es[(b * Hn + hh) * Nn + n0 + n] = p[hh];
                g_ed[(b * Hn + hh) * Nn + n0 + n] = p[4 + hh];
            }
        }
    }
    __syncthreads();

    const int hh = warp & 3;
    const int dh = warp >> 2;
    const int g  = lane >> 2;
    const int qt = lane & 3;
    const __half* Wt = g_W16T + ((size_t)hh * Dn + dh * 16) * Fn;

    float C[4][4];
    #pragma unroll
    for (int nt = 0; nt < 4; nt++)
        #pragma unroll
        for (int k = 0; k < 4; k++) C[nt][k] = 0.f;

    #pragma unroll
    for (int ks = 0; ks < 8; ks++) {
        const int fk = ks * 16 + 2 * qt;
        const uint32_t a0 = *(const uint32_t*)(Wt + (size_t)g * Fn + fk);
        const uint32_t a1 = *(const uint32_t*)(Wt + (size_t)(g + 8) * Fn + fk);
        const uint32_t a2 = *(const uint32_t*)(Wt + (size_t)g * Fn + fk + 8);
        const uint32_t a3 = *(const uint32_t*)(Wt + (size_t)(g + 8) * Fn + fk + 8);
        #pragma unroll
        for (int nt = 0; nt < 4; nt++) {
            const uint32_t b0 = *(const uint32_t*)&h16[(nt * 8 + g) * PPAD + fk];
            const uint32_t b1 = *(const uint32_t*)&h16[(nt * 8 + g) * PPAD + fk + 8];
            asm volatile(
                "mma.sync.aligned.m16n8k16.row.col.f32.f16.f16.f32 "
                "{%0,%1,%2,%3}, {%4,%5,%6,%7}, {%8,%9}, {%0,%1,%2,%3};"
                : "+f"(C[nt][0]), "+f"(C[nt][1]), "+f"(C[nt][2]), "+f"(C[nt][3])
                : "r"(a0), "r"(a1), "r"(a2), "r"(a3), "r"(b0), "r"(b1));
        }
    }

    const int bh = b * Hn + hh;
    uint32_t* w0 = (uint32_t*)g_WhT + (((size_t)bh * Dn + dh * 16 + g) * Nn + n0) / 2;
    uint32_t* w8 = w0 + 8 * (Nn / 2);
    #pragma unroll
    for (int nt = 0; nt < 4; nt++) {
        const int widx = (nt >> 1) * 8 + 2 * qt + (nt & 1);
        uint32_t lo, hi;
        asm("cvt.rn.f16x2.f32 %0, %1, %2;" : "=r"(lo) : "f"(C[nt][1]), "f"(C[nt][0]));
        asm("cvt.rn.f16x2.f32 %0, %1, %2;" : "=r"(hi) : "f"(C[nt][3]), "f"(C[nt][2]));
        w0[widx] = lo;
        w8[widx] = hi;
    }
}

// -------------------- Kernel B: masked softmax + P@Wh via fp16 MMA --------------------
#define TJm 128
#define NMT (Nn / TJm)
#define WSTh 144
#define CST 34

__global__ __launch_bounds__(256, 3) void attn_kernel(float* __restrict__ out)
{
    __shared__ __align__(16) float    ed_sm[Nn];             // 8 KB
    __shared__ __align__(16) unsigned mask_sm[64 * 64];      // 16 KB (cp.async from g_mask; C scratch later)
    __shared__ __align__(16) __half   wh_sm[2][32 * WSTh];   // 18 KB double buffer
    __shared__ float es1_sm[64], es2_sm[64];

    const int bh = blockIdx.x;
    const int b  = bh >> 2;
    const int hd = bh & 3;
    const int rbase = blockIdx.y * 64;
    const int tid  = threadIdx.x;
    const int warp = tid >> 5;
    const int lane = tid & 31;
    const int g  = lane >> 2;
    const int qt = lane & 3;
    const int par = warp >> 2;
    const int lrA = (warp & 3) * 16 + g;
    const int lrB = lrA + 8;
    const unsigned lanebit = 1u << lane;

    const __half* whg = g_WhT + (size_t)bh * Dn * Nn;

    // ---- group 0: cp.async adjacency masks (16 KB) ----
    #pragma unroll
    for (int tt = 0; tt < 4; tt++) {
        const int idx = tid + tt * 256;
        uint32_t dp = (uint32_t)__cvta_generic_to_shared(&mask_sm[idx * 4]);
        asm volatile("cp.async.ca.shared.global [%0], [%1], 16;"
                     :: "r"(dp), "l"(&g_mask[(size_t)rbase * 64 + idx * 4]));
    }
    asm volatile("cp.async.commit_group;" ::: "memory");

    // ---- stage e_dst (scaled to log2 units) ----
    {
        const float4* src = (const float4*)(g_ed + bh * Nn);
        float4* dst = (float4*)ed_sm;
        #pragma unroll
        for (int r = 0; r < 2; r++) {
            float4 v = src[tid + r * 256];
            v.x *= LOG2E; v.y *= LOG2E; v.z *= LOG2E; v.w *= LOG2E;
            dst[tid + r * 256] = v;
        }
    }

    // ---- groups 1,2: prefetch WhT metas 0,1 ----
    #pragma unroll
    for (int c = 0; c < 2; c++) {
        #pragma unroll
        for (int tt = 0; tt < 2; tt++) {
            const int idx = tid + tt * 256;
            const int row = idx >> 4, seg = idx & 15;
            uint32_t dp = (uint32_t)__cvta_generic_to_shared(&wh_sm[c][row * WSTh + seg * 8]);
            asm volatile("cp.async.ca.shared.global [%0], [%1], 16;"
                         :: "r"(dp), "l"(whg + (size_t)row * Nn + c * TJm + seg * 8));
        }
        asm volatile("cp.async.commit_group;" ::: "memory");
    }

    asm volatile("cp.async.wait_group 2;" ::: "memory");   // masks landed
    __syncthreads();   // ed_sm + mask_sm ready

    // ---- Pass 1: exact masked row max from precomputed bitmasks ----
    for (int k = 0; k < 8; k++) {
        const int lr = warp * 8 + k;
        float m = -1e30f;
        #pragma unroll
        for (int it = 0; it < 16; it++) {
            const uint4 mw = *(const uint4*)&mask_sm[lr * 64 + it * 4];   // broadcast
            const float4 ev = *(const float4*)&ed_sm[it * 128 + lane * 4];
            if (mw.x & lanebit) m = fmaxf(m, ev.x);
            if (mw.y & lanebit) m = fmaxf(m, ev.y);
            if (mw.z & lanebit) m = fmaxf(m, ev.z);
            if (mw.w & lanebit) m = fmaxf(m, ev.w);
        }
        #pragma unroll
        for (int off = 16; off; off >>= 1) m = fmaxf(m, __shfl_xor_sync(FULLM, m, off));
        if (lane == 0) {
            const float es = __ldg(g_es + bh * Nn + rbase + lr) * LOG2E;
            float e1, e2;
            if (m < -9e29f) { e1 = -1e9f; e2 = -1e9f; }
            else {
                float s = es + m;
                float M = fmaxf(s, 0.2f * s);
                e1 = es - M;
                e2 = 0.2f * es - M;
            }
            es1_sm[lr] = e1; es2_sm[lr] = e2;
        }
    }
    __syncthreads();

    const ull esA1x2 = pack2(es1_sm[lrA]), esA2x2 = pack2(es2_sm[lrA]);
    const ull esB1x2 = pack2(es1_sm[lrB]), esB2x2 = pack2(es2_sm[lrB]);
    const ull C02 = pack2(0.2f);

    // ---- Pass 2: P (fp16 A-fragment) @ WhT via mma.m16n8k16; tile 4 yields l ----
    float C[5][4];
    #pragma unroll
    for (int nt = 0; nt < 5; nt++)
        #pragma unroll
        for (int k = 0; k < 4; k++) C[nt][k] = 0.f;

    const int c0 = 2 * (qt & 1);
    const int psh = par * 16 + (qt >> 1);
    const uint32_t blx = (g == 0) ? 0x3C003C00u : 0u;   // constant ones-column B-fragment

    for (int t = 0; t < NMT; t++) {
        asm volatile("cp.async.wait_group 1;" ::: "memory");
        __syncthreads();

        const uint2 mwA = *(const uint2*)&mask_sm[lrA * 64 + (t << 2) + c0];
        const uint2 mwB = *(const uint2*)&mask_sm[lrB * 64 + (t << 2) + c0];
        const unsigned wA0 = mwA.x >> psh;
        const unsigned wA1 = mwA.y >> psh;
        const unsigned wB0 = mwB.x >> psh;
        const unsigned wB1 = mwB.y >> psh;
        const int jb = t * TJm + par * 64;
        const __half* wbuf = wh_sm[t & 1] + par * 64;

        #pragma unroll
        for (int ks = 0; ks < 4; ks++) {
            const int j0 = jb + ks * 16 + 2 * qt;
            const ull ed2lo = *(const ull*)(ed_sm + j0);
            const ull ed2hi = *(const ull*)(ed_sm + j0 + 8);
            float aA0, aA1, aA8, aA9, aB0, aB1, aB8, aB9;
            score2(ed2lo, esA1x2, esA2x2, C02, aA0, aA1);
            score2(ed2hi, esA1x2, esA2x2, C02, aA8, aA9);
            score2(ed2lo, esB1x2, esB2x2, C02, aB0, aB1);
            score2(ed2hi, esB1x2, esB2x2, C02, aB8, aB9);
            float pA0 = 0.f, pA1 = 0.f, pA8 = 0.f, pA9 = 0.f;
            float pB0 = 0.f, pB1 = 0.f, pB8 = 0.f, pB9 = 0.f;
            if (wA0 & (1u << (4 * ks)))     pA0 = ex2(aA0);
            if (wA1 & (1u << (4 * ks)))     pA1 = ex2(aA1);
            if (wA0 & (1u << (4 * ks + 2))) pA8 = ex2(aA8);
            if (wA1 & (1u << (4 * ks + 2))) pA9 = ex2(aA9);
            if (wB0 & (1u << (4 * ks)))     pB0 = ex2(aB0);
            if (wB1 & (1u << (4 * ks)))     pB1 = ex2(aB1);
            if (wB0 & (1u << (4 * ks + 2))) pB8 = ex2(aB8);
            if (wB1 & (1u << (4 * ks + 2))) pB9 = ex2(aB9);
            uint32_t a0, a1, a2, a3;
            asm("cvt.rn.f16x2.f32 %0, %1, %2;" : "=r"(a0) : "f"(pA1), "f"(pA0));
            asm("cvt.rn.f16x2.f32 %0, %1, %2;" : "=r"(a1) : "f"(pB1), "f"(pB0));
            asm("cvt.rn.f16x2.f32 %0, %1, %2;" : "=r"(a2) : "f"(pA9), "f"(pA8));
            asm("cvt.rn.f16x2.f32 %0, %1, %2;" : "=r"(a3) : "f"(pB9), "f"(pB8));
            const __half* bpt = wbuf + ks * 16 + 4 * qt;
            #pragma unroll
            for (int nt = 0; nt < 4; nt++) {
                const uint2 bb = *(const uint2*)(bpt + (nt * 8 + g) * WSTh);
                asm volatile(
                    "mma.sync.aligned.m16n8k16.row.col.f32.f16.f16.f32 "
                    "{%0,%1,%2,%3}, {%4,%5,%6,%7}, {%8,%9}, {%0,%1,%2,%3};"
                    : "+f"(C[nt][0]), "+f"(C[nt][1]), "+f"(C[nt][2]), "+f"(C[nt][3])
                    : "r"(a0), "r"(a1), "r"(a2), "r"(a3), "r"(bb.x), "r"(bb.y));
            }
            asm volatile(
                "mma.sync.aligned.m16n8k16.row.col.f32.f16.f16.f32 "
                "{%0,%1,%2,%3}, {%4,%5,%6,%7}, {%8,%9}, {%0,%1,%2,%3};"
                : "+f"(C[4][0]), "+f"(C[4][1]), "+f"(C[4][2]), "+f"(C[4][3])
                : "r"(a0), "r"(a1), "r"(a2), "r"(a3), "r"(blx), "r"(blx));
        }

        __syncthreads();
        const int nc = t + 2;
        if (nc < NMT) {
            #pragma unroll
            for (int tt = 0; tt < 2; tt++) {
                const int idx = tid + tt * 256;
                const int row = idx >> 4, seg = idx & 15;
                uint32_t dp = (uint32_t)__cvta_generic_to_shared(&wh_sm[nc & 1][row * WSTh + seg * 8]);
                asm volatile("cp.async.ca.shared.global [%0], [%1], 16;"
                             :: "r"(dp), "l"(whg + (size_t)row * Nn + nc * TJm + seg * 8));
            }
        }
        asm volatile("cp.async.commit_group;" ::: "memory");
    }

    const float lA = __shfl_sync(FULLM, C[4][0], lane & ~3);
    const float lB = __shfl_sync(FULLM, C[4][2], lane & ~3);

    // ---- Combine the two j-halves (warps w and w+4 hold the same rows) ----
    float* Csc = (float*)mask_sm;
    float* lsc = Csc + 64 * CST;
    if (par == 1) {
        #pragma unroll
        for (int nt = 0; nt < 4; nt++) {
            *(float2*)&Csc[lrA * CST + nt * 8 + 2 * qt] = make_float2(C[nt][0], C[nt][1]);
            *(float2*)&Csc[lrB * CST + nt * 8 + 2 * qt] = make_float2(C[nt][2], C[nt][3]);
        }
        if (qt == 0) { lsc[lrA] = lA; lsc[lrB] = lB; }
    }
    __syncthreads();
    if (par == 0) {
        #pragma unroll
        for (int nt = 0; nt < 4; nt++) {
            float2 cA = *(const float2*)&Csc[lrA * CST + nt * 8 + 2 * qt];
            float2 cB = *(const float2*)&Csc[lrB * CST + nt * 8 + 2 * qt];
            C[nt][0] += cA.x; C[nt][1] += cA.y;
            C[nt][2] += cB.x; C[nt][3] += cB.y;
        }
        const float tlA = lA + lsc[lrA];
        const float tlB = lB + lsc[lrB];
        const float rlA = (tlA > 0.f) ? (1.f / tlA) : 0.f;
        const float rlB = (tlB > 0.f) ? (1.f / tlB) : 0.f;
        const int iA = rbase + lrA;
        const int iB = rbase + lrB;
        float* outA = out + (size_t)(b * Nn + iA) * (Hn * Dn) + hd * Dn + 2 * qt;
        float* outB = out + (size_t)(b * Nn + iB) * (Hn * Dn) + hd * Dn + 2 * qt;
        #pragma unroll
        for (int nt = 0; nt < 4; nt++) {
            *(float2*)(outA + nt * 8) = make_float2(C[nt][0] * rlA, C[nt][1] * rlA);
            *(float2*)(outB + nt * 8) = make_float2(C[nt][2] * rlB, C[nt][3] * rlB);
        }
    }
}

extern "C" void kernel_launch(void* const* d_in, const int* in_sizes, int n_in,
                              void* d_out, int out_size)
{
    // Bind inputs by element count (robust to metadata ordering)
    const float* h = nullptr; const int* adj = nullptr;
    const float* W = nullptr; const float* a = nullptr;
    for (int i = 0; i < n_in; i++) {
        switch (in_sizes[i]) {
            case 1048576: h   = (const float*)d_in[i]; break;
            case 4194304: adj = (const int*)  d_in[i]; break;
            case 16384:   W   = (const float*)d_in[i]; break;
            case 256:     a   = (const float*)d_in[i]; break;
        }
    }
    float* out = (float*)d_out;

    setup_kernel<<<80, 256>>>(W, a, adj);
    proj_kernel<<<dim3(Bn, Nn / 32), 256>>>(h);
    attn_kernel<<<dim3(BH, Nn / 64), 256>>>(out);
}